// round 11
// baseline (speedup 1.0000x reference)
#include <cuda_runtime.h>
#include <cuda_fp16.h>
#include <math_constants.h>
#include <cstdint>

#define HID 1024
#define NHEADS 16
#define HDIM 64
#define SEQ 2048
#define BT 8192
#define K2 2048            // split-GEMM K' = 2*HID (fp16 hi/lo)
#define GSTEPS (K2 / 64)   // 32 k-steps of 64 fp16

// ---------------------------------------------------------------------------
// Scratch (__device__ globals: runtime allocation is forbidden)
// ---------------------------------------------------------------------------
__device__ __half g_a2x[(size_t)BT * K2];          // [Ah|Al] of x
__device__ __half g_w2qkv[(size_t)3 * HID * K2];   // [Wh|Wh] of W_qkv
__device__ __half g_a2ctx[(size_t)BT * K2];        // [ctx_h|ctx_l]
__device__ __half g_w2out[(size_t)HID * K2];       // [Wh|Wh] of W_out
__device__ __half g_qh[(size_t)BT * 3 * HID];      // qkv hi (fp16)
__device__ __half g_ql[(size_t)BT * 3 * HID];      // qkv lo (fp16)

// ---------------------------------------------------------------------------
// helpers
// ---------------------------------------------------------------------------
__device__ __forceinline__ uint32_t smem_to_u32(const void* p) {
    uint32_t a;
    asm("{ .reg .u64 t; cvta.to.shared.u64 t, %1; cvt.u32.u64 %0, t; }"
        : "=r"(a) : "l"(p));
    return a;
}
#define SW128(b) ((b) ^ (((b) >> 3) & 0x70u))

__device__ __forceinline__ void ldsm_x4(uint32_t* r, uint32_t addr) {
    asm volatile("ldmatrix.sync.aligned.m8n8.x4.shared.b16 {%0,%1,%2,%3}, [%4];"
        : "=r"(r[0]), "=r"(r[1]), "=r"(r[2]), "=r"(r[3]) : "r"(addr));
}
__device__ __forceinline__ void ldsm_x4_t(uint32_t* r, uint32_t addr) {
    asm volatile("ldmatrix.sync.aligned.m8n8.x4.trans.shared.b16 {%0,%1,%2,%3}, [%4];"
        : "=r"(r[0]), "=r"(r[1]), "=r"(r[2]), "=r"(r[3]) : "r"(addr));
}
__device__ __forceinline__ void mma16816(float* d, const uint32_t* a, const uint32_t* b) {
    asm volatile("mma.sync.aligned.m16n8k16.row.col.f32.f16.f16.f32 "
        "{%0,%1,%2,%3}, {%4,%5,%6,%7}, {%8,%9}, {%0,%1,%2,%3};"
        : "+f"(d[0]), "+f"(d[1]), "+f"(d[2]), "+f"(d[3])
        : "r"(a[0]), "r"(a[1]), "r"(a[2]), "r"(a[3]), "r"(b[0]), "r"(b[1]));
}
__device__ __forceinline__ void cp16(uint32_t dst, const void* src) {
    asm volatile("cp.async.cg.shared.global [%0], [%1], 16;" :: "r"(dst), "l"(src));
}
__device__ __forceinline__ void cp_commit() { asm volatile("cp.async.commit_group;" ::: "memory"); }
__device__ __forceinline__ void cp_wait1()  { asm volatile("cp.async.wait_group 1;" ::: "memory"); }
__device__ __forceinline__ void cp_wait0()  { asm volatile("cp.async.wait_group 0;" ::: "memory"); }

__device__ __forceinline__ uint32_t pack2h(float a, float b) {
    __half2 t = __floats2half2_rn(a, b);
    return *reinterpret_cast<uint32_t*>(&t);
}
__device__ __forceinline__ float hround(float v) {
    return __half2float(__float2half_rn(v));
}

// ---------------------------------------------------------------------------
// Split convert: src fp32 [rows, K] -> dst fp16 [rows, 2K]
// blk0 = hi always.  blk1 = lo (A-side, dup_hi=0) or hi (W-side, dup_hi=1).
// ---------------------------------------------------------------------------
__global__ __launch_bounds__(256) void split_kernel(
    const float* __restrict__ src, __half* __restrict__ dst,
    int K, size_t total4, int dup_hi)
{
    size_t idx = (size_t)blockIdx.x * blockDim.x + threadIdx.x;
    if (idx >= total4) return;
    int kq = K >> 2;
    size_t r = idx / kq;
    int c = (int)(idx % kq) << 2;
    float4 v = *(const float4*)(src + r * K + c);

    float h0 = hround(v.x), h1 = hround(v.y), h2 = hround(v.z), h3 = hround(v.w);
    uint2 hi = make_uint2(pack2h(h0, h1), pack2h(h2, h3));
    uint2 lo = make_uint2(pack2h(v.x - h0, v.y - h1), pack2h(v.z - h2, v.w - h3));

    __half* drow = dst + r * (size_t)(2 * K);
    *(uint2*)(drow + c) = hi;
    *(uint2*)(drow + K + c) = dup_hi ? hi : lo;
}

// ---------------------------------------------------------------------------
// mma.sync fp16 GEMM: C[M,N] = A2[M,K2] @ W2[N,K2]^T + bias
// CTA 128x128, BK=64, 256 thr (8 warps 2x4), warp tile 64x32.
// 3-stage cp.async ring; odd warps run kat order 2,3,0,1 so half the warps
// LDSM while the other half MMA (overlap crossbar with tensor pipe).
// ---------------------------------------------------------------------------
__global__ __launch_bounds__(256, 2) void gemm_mma_kernel(
    const __half* __restrict__ A2, const __half* __restrict__ W2,
    const float* __restrict__ bias, float* __restrict__ Cf,
    __half* __restrict__ Ch, __half* __restrict__ Cl, int N)
{
    extern __shared__ char dsm[];
    const uint32_t dyn = smem_to_u32(dsm);
    const uint32_t base = (dyn + 1023u) & ~1023u;

    const int tid = threadIdx.x;
    const int lane = tid & 31;
    const int wid = tid >> 5;
    const int wm = wid >> 2;
    const int wn = wid & 3;
    const int kx = (wid & 1) << 1;    // phase stagger: 0 or 2
    const size_t m0 = (size_t)blockIdx.y * 128;
    const size_t n0 = (size_t)blockIdx.x * 128;

    const int arow = tid >> 1;
    const int ahalf = tid & 1;
    const __half* gA = A2 + (m0 + arow) * K2 + ahalf * 32;
    const __half* gB = W2 + (n0 + arow) * K2 + ahalf * 32;
    const uint32_t sts = (uint32_t)(arow * 128 + ahalf * 64);

    float acc[4][4][4];
#pragma unroll
    for (int i = 0; i < 4; i++)
#pragma unroll
        for (int j = 0; j < 4; j++)
#pragma unroll
            for (int r = 0; r < 4; r++) acc[i][j][r] = 0.f;

    auto issue = [&](int s) {
        const uint32_t ab = base + (uint32_t)(s % 3) * 32768u;
        const int k0 = s * 64;
#pragma unroll
        for (int c = 0; c < 4; c++) {
            const uint32_t sw = SW128(sts + (uint32_t)c * 16u);
            cp16(ab + sw, gA + k0 + c * 8);
            cp16(ab + 16384u + sw, gB + k0 + c * 8);
        }
    };

    issue(0); cp_commit();
    issue(1); cp_commit();

#pragma unroll 1
    for (int s = 0; s < GSTEPS; s++) {
        cp_wait1();              // stage s resident (stage s+1 may be pending)
        __syncthreads();         // all warps see stage s; all done with stage s-1
        if (s + 2 < GSTEPS) issue(s + 2);   // ring distance 2
        cp_commit();

        const uint32_t abase = base + (uint32_t)(s % 3) * 32768u;
        const uint32_t bbase = abase + 16384u;
#pragma unroll
        for (int kk = 0; kk < 4; kk++) {
            const int kat = kk ^ kx;      // warp-staggered kat order
            uint32_t af[4][4], bf[4][2];
#pragma unroll
            for (int i = 0; i < 4; i++) {
                uint32_t row = (uint32_t)(wm * 64 + i * 16 + (lane & 15));
                uint32_t byte = row * 128u + (uint32_t)kat * 32u + ((lane >> 4) << 4);
                ldsm_x4(af[i], abase + SW128(byte));
            }
#pragma unroll
            for (int jj = 0; jj < 2; jj++) {
                uint32_t row = (uint32_t)(wn * 32 + jj * 16 + ((lane >> 4) & 1) * 8 + (lane & 7));
                uint32_t byte = row * 128u + (uint32_t)kat * 32u + (((lane >> 3) & 1) << 4);
                uint32_t t[4];
                ldsm_x4(t, bbase + SW128(byte));
                bf[jj * 2][0] = t[0]; bf[jj * 2][1] = t[1];
                bf[jj * 2 + 1][0] = t[2]; bf[jj * 2 + 1][1] = t[3];
            }
#pragma unroll
            for (int i = 0; i < 4; i++)
#pragma unroll
                for (int j = 0; j < 4; j++)
                    mma16816(acc[i][j], af[i], bf[j]);
        }
    }

    // epilogue
    const int g = lane >> 2;
    const int tig = lane & 3;
#pragma unroll
    for (int i = 0; i < 4; i++) {
        const size_t r0 = m0 + wm * 64 + i * 16 + g;
#pragma unroll
        for (int j = 0; j < 4; j++) {
            const int col = (int)n0 + wn * 32 + j * 8 + tig * 2;
            const float2 bb = *(const float2*)(bias + col);
            const float v0 = acc[i][j][0] + bb.x, v1 = acc[i][j][1] + bb.y;
            const float v2 = acc[i][j][2] + bb.x, v3 = acc[i][j][3] + bb.y;
            if (Cf) {
                *(float2*)(Cf + r0 * N + col) = make_float2(v0, v1);
                *(float2*)(Cf + (r0 + 8) * N + col) = make_float2(v2, v3);
            } else {
                const float h0 = hround(v0), h1 = hround(v1);
                const float h2 = hround(v2), h3 = hround(v3);
                *(uint32_t*)(Ch + r0 * N + col) = pack2h(h0, h1);
                *(uint32_t*)(Cl + r0 * N + col) = pack2h(v0 - h0, v1 - h1);
                *(uint32_t*)(Ch + (r0 + 8) * N + col) = pack2h(h2, h3);
                *(uint32_t*)(Cl + (r0 + 8) * N + col) = pack2h(v2 - h2, v3 - h3);
            }
        }
    }
}

// ---------------------------------------------------------------------------
// Fused causal flash attention on tensor cores (fp16 split).
// grid (16 qtiles, 64 bh), 256 thr (8 warps), warp = 16 q-rows.
// S = 0.125*(Qh·Kh + Ql·Kh);  O += Ph·Vh + Pl·Vh.   (K,V quantized: err~2^-12)
// K/V double-buffered cp.async; warp-staggered kat order in S and O loops.
// smem: Qh,Ql 32KB + 2 x (Kh,Vh 16KB) = 64KB.
// ---------------------------------------------------------------------------
__global__ __launch_bounds__(256, 2) void attn_mma_kernel(
    const __half* __restrict__ qh_g, const __half* __restrict__ ql_g,
    __half* __restrict__ a2ctx)
{
    extern __shared__ char smA[];
    const uint32_t dyn = smem_to_u32(smA);
    const uint32_t sb = (dyn + 1023u) & ~1023u;
    char* p = smA + (sb - dyn);
    const uint32_t QH = sb, QL = sb + 16384u;

    const int tid = threadIdx.x;
    const int lane = tid & 31;
    const int w = tid >> 5;
    const int g = lane >> 2;
    const int tig = lane & 3;
    const int kx = (w & 1) << 1;      // phase stagger
    const int qt = blockIdx.x;
    const int bh = blockIdx.y;
    const int b = bh >> 4;
    const int hd = bh & 15;
    const int q0 = qt * 128;
    const int qw = q0 + w * 16;

    // K/V cp.async: tile = tid>>7 (0=Kh from +1024, 1=Vh from +2048), 2 thr/row
    const int kv_tile = tid >> 7;
    const int kv_r = (tid >> 1) & 63;
    const int kv_h = tid & 1;
    const __half* kv_src_base = qh_g + ((size_t)b * SEQ + kv_r) * 3072
        + (kv_tile ? 2048 : 1024) + hd * 64 + kv_h * 32;
    auto issue_kv = [&](int kt) {
        const uint32_t dst = sb + 32768u + (uint32_t)(kt & 1) * 16384u + (uint32_t)kv_tile * 8192u;
        const __half* src = kv_src_base + (size_t)kt * 64 * 3072;
#pragma unroll
        for (int c = 0; c < 4; c++)
            cp16(dst + SW128((uint32_t)(kv_r * 128 + kv_h * 64 + c * 16)), src + c * 8);
    };

    // Q tiles (hi, lo): 128 rows x 128B each (plain stores; covered by 1st barrier)
    {
        const int r = tid & 127;
        const int buf = tid >> 7;
        const __half* src = (buf ? ql_g : qh_g)
            + ((size_t)b * SEQ + q0 + r) * 3072 + hd * 64;
        char* dst = p + buf * 16384;
#pragma unroll
        for (int c = 0; c < 8; c++)
            *(uint4*)(dst + SW128((uint32_t)(r * 128 + c * 16))) = *(const uint4*)(src + c * 8);
    }

    issue_kv(0); cp_commit();

    float S[32], O[32];
#pragma unroll
    for (int i = 0; i < 32; i++) O[i] = 0.f;
    float m0 = -CUDART_INF_F, m1 = -CUDART_INF_F, l0 = 0.f, l1 = 0.f;

    const int ktmax = 2 * (qt + 1);
#pragma unroll 1
    for (int kt = 0; kt < ktmax; kt++) {
        const int k0 = kt * 64;
        cp_wait0();              // K/V stage kt resident
        __syncthreads();         // visible to all; all done with stage kt-1
        if (kt + 1 < ktmax) issue_kv(kt + 1);   // overlaps compute of kt
        cp_commit();

        const uint32_t kvb = sb + 32768u + (uint32_t)(kt & 1) * 16384u;
        const uint32_t KH = kvb, VH = kvb + 8192u;

        if (k0 <= qw + 15) {
#pragma unroll
            for (int i = 0; i < 32; i++) S[i] = 0.f;
            // ---- S = Qh·Kh + Ql·Kh   (warp-staggered kat order)
#pragma unroll
            for (int kk = 0; kk < 4; kk++) {
                const int kat = kk ^ kx;
                const uint32_t swzA = SW128((uint32_t)((w * 16 + (lane & 15)) * 128
                                       + kat * 32 + ((lane >> 4) << 4)));
                uint32_t aqh[4], aql[4];
                ldsm_x4(aqh, QH + swzA);
                ldsm_x4(aql, QL + swzA);
#pragma unroll
                for (int j2 = 0; j2 < 4; j2++) {
                    const uint32_t swzB = SW128((uint32_t)((j2 * 16 + ((lane >> 4) & 1) * 8
                                            + (lane & 7)) * 128 + kat * 32 + ((lane >> 3) & 1) * 16));
                    uint32_t bkh[4];
                    ldsm_x4(bkh, KH + swzB);
                    mma16816(&S[(2 * j2) * 4], aqh, bkh);
                    mma16816(&S[(2 * j2 + 1) * 4], aqh, bkh + 2);
                    mma16816(&S[(2 * j2) * 4], aql, bkh);
                    mma16816(&S[(2 * j2 + 1) * 4], aql, bkh + 2);
                }
            }
            // ---- scale + causal mask + online softmax
            const int row0 = qw + g, row1 = row0 + 8;
            const bool msk = (k0 + 63 > qw);
            float tm0 = -CUDART_INF_F, tm1 = -CUDART_INF_F;
#pragma unroll
            for (int j = 0; j < 8; j++) {
                float* sj = &S[j * 4];
                sj[0] *= 0.125f; sj[1] *= 0.125f; sj[2] *= 0.125f; sj[3] *= 0.125f;
                if (msk) {
                    const int c0 = k0 + j * 8 + 2 * tig;
                    if (c0 > row0)     sj[0] = -CUDART_INF_F;
                    if (c0 + 1 > row0) sj[1] = -CUDART_INF_F;
                    if (c0 > row1)     sj[2] = -CUDART_INF_F;
                    if (c0 + 1 > row1) sj[3] = -CUDART_INF_F;
                }
                tm0 = fmaxf(tm0, fmaxf(sj[0], sj[1]));
                tm1 = fmaxf(tm1, fmaxf(sj[2], sj[3]));
            }
            tm0 = fmaxf(tm0, __shfl_xor_sync(0xffffffffu, tm0, 1));
            tm0 = fmaxf(tm0, __shfl_xor_sync(0xffffffffu, tm0, 2));
            tm1 = fmaxf(tm1, __shfl_xor_sync(0xffffffffu, tm1, 1));
            tm1 = fmaxf(tm1, __shfl_xor_sync(0xffffffffu, tm1, 2));
            const float mn0 = fmaxf(m0, tm0), mn1 = fmaxf(m1, tm1);
            const float corr0 = __expf(m0 - mn0), corr1 = __expf(m1 - mn1);
            m0 = mn0; m1 = mn1;

            float ls0 = 0.f, ls1 = 0.f;
            uint32_t PHf[16], PLf[16];
#pragma unroll
            for (int j = 0; j < 8; j++) {
                const float e0 = __expf(S[j * 4 + 0] - mn0);
                const float e1 = __expf(S[j * 4 + 1] - mn0);
                const float e2 = __expf(S[j * 4 + 2] - mn1);
                const float e3 = __expf(S[j * 4 + 3] - mn1);
                ls0 += e0 + e1; ls1 += e2 + e3;
                const float h0 = hround(e0), h1 = hround(e1);
                const float h2 = hround(e2), h3 = hround(e3);
                PHf[j * 2 + 0] = pack2h(h0, h1);
                PHf[j * 2 + 1] = pack2h(h2, h3);
                PLf[j * 2 + 0] = pack2h(e0 - h0, e1 - h1);
                PLf[j * 2 + 1] = pack2h(e2 - h2, e3 - h3);
            }
            ls0 += __shfl_xor_sync(0xffffffffu, ls0, 1);
            ls0 += __shfl_xor_sync(0xffffffffu, ls0, 2);
            ls1 += __shfl_xor_sync(0xffffffffu, ls1, 1);
            ls1 += __shfl_xor_sync(0xffffffffu, ls1, 2);
            l0 = l0 * corr0 + ls0;
            l1 = l1 * corr1 + ls1;
#pragma unroll
            for (int j = 0; j < 8; j++) {
                O[j * 4 + 0] *= corr0; O[j * 4 + 1] *= corr0;
                O[j * 4 + 2] *= corr1; O[j * 4 + 3] *= corr1;
            }
            // ---- O += Ph·Vh + Pl·Vh   (V^T via ldmatrix.trans; staggered kat)
#pragma unroll
            for (int kk = 0; kk < 4; kk++) {
                const int kat = kk ^ kx;
#pragma unroll
                for (int jd2 = 0; jd2 < 4; jd2++) {
                    const uint32_t swzV = SW128((uint32_t)((kat * 16 + ((lane >> 3) & 1) * 8
                                            + (lane & 7)) * 128 + jd2 * 32 + ((lane >> 4) & 1) * 16));
                    uint32_t bvh[4];
                    ldsm_x4_t(bvh, VH + swzV);
                    mma16816(&O[(2 * jd2) * 4], &PHf[4 * kat], bvh);
                    mma16816(&O[(2 * jd2 + 1) * 4], &PHf[4 * kat], bvh + 2);
                    mma16816(&O[(2 * jd2) * 4], &PLf[4 * kat], bvh);
                    mma16816(&O[(2 * jd2 + 1) * 4], &PLf[4 * kat], bvh + 2);
                }
            }
        }
    }

    // epilogue: normalized O -> split ctx rows [hi | lo] (width 2048)
    const float inv0 = 1.f / l0, inv1 = 1.f / l1;
    __half* rp0 = a2ctx + ((size_t)b * SEQ + qw + g) * K2 + hd * 64;
    __half* rp1 = rp0 + (size_t)8 * K2;
#pragma unroll
    for (int j = 0; j < 8; j++) {
        const int c = j * 8 + 2 * tig;
        {
            const float v0 = O[j * 4 + 0] * inv0, v1 = O[j * 4 + 1] * inv0;
            const float h0 = hround(v0), h1 = hround(v1);
            *(uint32_t*)(rp0 + c) = pack2h(h0, h1);
            *(uint32_t*)(rp0 + 1024 + c) = pack2h(v0 - h0, v1 - h1);
        }
        {
            const float v2 = O[j * 4 + 2] * inv1, v3 = O[j * 4 + 3] * inv1;
            const float h2 = hround(v2), h3 = hround(v3);
            *(uint32_t*)(rp1 + c) = pack2h(h2, h3);
            *(uint32_t*)(rp1 + 1024 + c) = pack2h(v2 - h2, v3 - h3);
        }
    }
}

// ---------------------------------------------------------------------------
extern "C" void kernel_launch(void* const* d_in, const int* in_sizes, int n_in,
                              void* d_out, int out_size)
{
    (void)in_sizes; (void)n_in; (void)out_size;
    const float* x     = (const float*)d_in[0];
    const float* W_qkv = (const float*)d_in[2];
    const float* b_qkv = (const float*)d_in[3];
    const float* W_out = (const float*)d_in[4];
    const float* b_out = (const float*)d_in[5];
    float* out = (float*)d_out;

    __half *a2x, *w2qkv, *a2ctx, *w2out, *qh, *ql;
    cudaGetSymbolAddress((void**)&a2x, g_a2x);
    cudaGetSymbolAddress((void**)&w2qkv, g_w2qkv);
    cudaGetSymbolAddress((void**)&a2ctx, g_a2ctx);
    cudaGetSymbolAddress((void**)&w2out, g_w2out);
    cudaGetSymbolAddress((void**)&qh, g_qh);
    cudaGetSymbolAddress((void**)&ql, g_ql);

    const int gsmem = 97 * 1024;   // 3x32KB ring + align
    const int asmem = 66 * 1024;   // 32KB Q + 2x16KB KV + align
    cudaFuncSetAttribute(gemm_mma_kernel, cudaFuncAttributeMaxDynamicSharedMemorySize, gsmem);
    cudaFuncSetAttribute(gemm_mma_kernel, cudaFuncAttributePreferredSharedMemoryCarveout, 100);
    cudaFuncSetAttribute(attn_mma_kernel, cudaFuncAttributeMaxDynamicSharedMemorySize, asmem);
    cudaFuncSetAttribute(attn_mma_kernel, cudaFuncAttributePreferredSharedMemoryCarveout, 100);

    // 0) split-precision conversions (fp16 hi/lo)
    split_kernel<<<(BT * HID / 4 + 255) / 256, 256>>>(x, a2x, HID, (size_t)BT * HID / 4, 0);
    split_kernel<<<(3 * HID * HID / 4 + 255) / 256, 256>>>(W_qkv, w2qkv, HID, (size_t)3 * HID * HID / 4, 1);
    split_kernel<<<(HID * HID / 4 + 255) / 256, 256>>>(W_out, w2out, HID, (size_t)HID * HID / 4, 1);

    // 1) QKV projection (HMMA fp16): [8192,2048] x [3072,2048]^T -> hi/lo fp16
    gemm_mma_kernel<<<dim3(3 * HID / 128, BT / 128), 256, gsmem>>>(
        a2x, w2qkv, b_qkv, nullptr, qh, ql, 3 * HID);

    // 2) fused causal attention (HMMA fp16 split) -> split-fp16 ctx
    attn_mma_kernel<<<dim3(SEQ / 128, 4 * NHEADS), 256, asmem>>>(qh, ql, a2ctx);

    // 3) output projection (HMMA fp16): [8192,2048] x [1024,2048]^T -> fp32 out
    gemm_mma_kernel<<<dim3(HID / 128, BT / 128), 256, gsmem>>>(
        a2ctx, w2out, b_out, out, nullptr, nullptr, HID);
}

// round 12
// speedup vs baseline: 1.0525x; 1.0525x over previous
#include <cuda_runtime.h>
#include <cuda_fp16.h>
#include <math_constants.h>
#include <cstdint>

#define HID 1024
#define NHEADS 16
#define HDIM 64
#define SEQ 2048
#define BT 8192
#define K2 2048            // split-GEMM K' = 2*HID (fp16 hi/lo)
#define GSTEPS (K2 / 64)   // 32 k-steps of 64 fp16

// ---------------------------------------------------------------------------
// Scratch (__device__ globals: runtime allocation is forbidden)
// ---------------------------------------------------------------------------
__device__ __half g_a2x[(size_t)BT * K2];          // [Ah|Al] of x
__device__ __half g_w2qkv[(size_t)3 * HID * K2];   // [Wh|Wh] of W_qkv
__device__ __half g_a2ctx[(size_t)BT * K2];        // [ctx_h|ctx_l]
__device__ __half g_w2out[(size_t)HID * K2];       // [Wh|Wh] of W_out
__device__ __half g_qh[(size_t)BT * 3 * HID];      // qkv hi (fp16)
__device__ __half g_ql[(size_t)BT * 3 * HID];      // qkv lo (fp16)

// ---------------------------------------------------------------------------
// helpers
// ---------------------------------------------------------------------------
__device__ __forceinline__ uint32_t smem_to_u32(const void* p) {
    uint32_t a;
    asm("{ .reg .u64 t; cvta.to.shared.u64 t, %1; cvt.u32.u64 %0, t; }"
        : "=r"(a) : "l"(p));
    return a;
}
#define SW128(b) ((b) ^ (((b) >> 3) & 0x70u))

__device__ __forceinline__ void ldsm_x4(uint32_t* r, uint32_t addr) {
    asm volatile("ldmatrix.sync.aligned.m8n8.x4.shared.b16 {%0,%1,%2,%3}, [%4];"
        : "=r"(r[0]), "=r"(r[1]), "=r"(r[2]), "=r"(r[3]) : "r"(addr));
}
__device__ __forceinline__ void ldsm_x4_t(uint32_t* r, uint32_t addr) {
    asm volatile("ldmatrix.sync.aligned.m8n8.x4.trans.shared.b16 {%0,%1,%2,%3}, [%4];"
        : "=r"(r[0]), "=r"(r[1]), "=r"(r[2]), "=r"(r[3]) : "r"(addr));
}
__device__ __forceinline__ void mma16816(float* d, const uint32_t* a, const uint32_t* b) {
    asm volatile("mma.sync.aligned.m16n8k16.row.col.f32.f16.f16.f32 "
        "{%0,%1,%2,%3}, {%4,%5,%6,%7}, {%8,%9}, {%0,%1,%2,%3};"
        : "+f"(d[0]), "+f"(d[1]), "+f"(d[2]), "+f"(d[3])
        : "r"(a[0]), "r"(a[1]), "r"(a[2]), "r"(a[3]), "r"(b[0]), "r"(b[1]));
}
__device__ __forceinline__ void cp16(uint32_t dst, const void* src) {
    asm volatile("cp.async.cg.shared.global [%0], [%1], 16;" :: "r"(dst), "l"(src));
}
__device__ __forceinline__ void cp_commit() { asm volatile("cp.async.commit_group;" ::: "memory"); }
__device__ __forceinline__ void cp_wait1()  { asm volatile("cp.async.wait_group 1;" ::: "memory"); }
__device__ __forceinline__ void cp_wait0()  { asm volatile("cp.async.wait_group 0;" ::: "memory"); }

__device__ __forceinline__ uint32_t pack2h(float a, float b) {
    __half2 t = __floats2half2_rn(a, b);
    return *reinterpret_cast<uint32_t*>(&t);
}
__device__ __forceinline__ float hround(float v) {
    return __half2float(__float2half_rn(v));
}

// ---------------------------------------------------------------------------
// Split convert: src fp32 [rows, K] -> dst fp16 [rows, 2K]
// blk0 = hi always.  blk1 = lo (A-side, dup_hi=0) or hi (W-side, dup_hi=1).
// ---------------------------------------------------------------------------
__global__ __launch_bounds__(256) void split_kernel(
    const float* __restrict__ src, __half* __restrict__ dst,
    int K, size_t total4, int dup_hi)
{
    size_t idx = (size_t)blockIdx.x * blockDim.x + threadIdx.x;
    if (idx >= total4) return;
    int kq = K >> 2;
    size_t r = idx / kq;
    int c = (int)(idx % kq) << 2;
    float4 v = *(const float4*)(src + r * K + c);

    float h0 = hround(v.x), h1 = hround(v.y), h2 = hround(v.z), h3 = hround(v.w);
    uint2 hi = make_uint2(pack2h(h0, h1), pack2h(h2, h3));
    uint2 lo = make_uint2(pack2h(v.x - h0, v.y - h1), pack2h(v.z - h2, v.w - h3));

    __half* drow = dst + r * (size_t)(2 * K);
    *(uint2*)(drow + c) = hi;
    *(uint2*)(drow + K + c) = dup_hi ? hi : lo;
}

// ---------------------------------------------------------------------------
// mma.sync fp16 GEMM: C[M,N] = A2[M,K2] @ W2[N,K2]^T + bias
// CTA 128x128, BK=64, 256 thr (8 warps 2x4), warp tile 64x32.
// 3-stage cp.async ring + REGISTER fragment double-buffer: kat k+1's LDSMs
// issue before kat k's MMAs, hiding LDSM latency under tensor work.
// ---------------------------------------------------------------------------
__global__ __launch_bounds__(256, 2) void gemm_mma_kernel(
    const __half* __restrict__ A2, const __half* __restrict__ W2,
    const float* __restrict__ bias, float* __restrict__ Cf,
    __half* __restrict__ Ch, __half* __restrict__ Cl, int N)
{
    extern __shared__ char dsm[];
    const uint32_t dyn = smem_to_u32(dsm);
    const uint32_t base = (dyn + 1023u) & ~1023u;

    const int tid = threadIdx.x;
    const int lane = tid & 31;
    const int wid = tid >> 5;
    const int wm = wid >> 2;
    const int wn = wid & 3;
    const size_t m0 = (size_t)blockIdx.y * 128;
    const size_t n0 = (size_t)blockIdx.x * 128;

    const int arow = tid >> 1;
    const int ahalf = tid & 1;
    const __half* gA = A2 + (m0 + arow) * K2 + ahalf * 32;
    const __half* gB = W2 + (n0 + arow) * K2 + ahalf * 32;
    const uint32_t sts = (uint32_t)(arow * 128 + ahalf * 64);

    // per-warp fragment source addresses (kat enters via XOR-safe low bits)
    const uint32_t aAddr = (uint32_t)((wm * 64 + (lane & 15)) * 128 + ((lane >> 4) << 4));
    const uint32_t bAddr = (uint32_t)((wn * 32 + ((lane >> 4) & 1) * 8 + (lane & 7)) * 128
                                      + (((lane >> 3) & 1) << 4));

    float acc[4][4][4];
#pragma unroll
    for (int i = 0; i < 4; i++)
#pragma unroll
        for (int j = 0; j < 4; j++)
#pragma unroll
            for (int r = 0; r < 4; r++) acc[i][j][r] = 0.f;

    auto issue = [&](int s) {
        const uint32_t ab = base + (uint32_t)(s % 3) * 32768u;
        const int k0 = s * 64;
#pragma unroll
        for (int c = 0; c < 4; c++) {
            const uint32_t sw = SW128(sts + (uint32_t)c * 16u);
            cp16(ab + sw, gA + k0 + c * 8);
            cp16(ab + 16384u + sw, gB + k0 + c * 8);
        }
    };

    issue(0); cp_commit();
    issue(1); cp_commit();

    uint32_t af[2][4][4], bf[2][4][2];

#pragma unroll 1
    for (int s = 0; s < GSTEPS; s++) {
        cp_wait1();              // stage s resident (stage s+1 may be pending)
        __syncthreads();         // all warps see stage s; all done with stage s-1
        if (s + 2 < GSTEPS) issue(s + 2);   // ring distance 2
        cp_commit();

        const uint32_t abase = base + (uint32_t)(s % 3) * 32768u;
        const uint32_t bbase = abase + 16384u;

        // prime fragment buffer 0 with kat=0
#pragma unroll
        for (int i = 0; i < 4; i++)
            ldsm_x4(af[0][i], abase + SW128(aAddr + (uint32_t)i * 2048u));
#pragma unroll
        for (int jj = 0; jj < 2; jj++) {
            uint32_t t[4];
            ldsm_x4(t, bbase + SW128(bAddr + (uint32_t)jj * 2048u));
            bf[0][jj * 2][0] = t[0]; bf[0][jj * 2][1] = t[1];
            bf[0][jj * 2 + 1][0] = t[2]; bf[0][jj * 2 + 1][1] = t[3];
        }

#pragma unroll
        for (int kk = 0; kk < 4; kk++) {
            const int cur = kk & 1, nxt = cur ^ 1;
            if (kk < 3) {   // prefetch kat kk+1 fragments BEFORE this kat's MMAs
                const uint32_t ko = (uint32_t)(kk + 1) * 32u;
#pragma unroll
                for (int i = 0; i < 4; i++)
                    ldsm_x4(af[nxt][i], abase + SW128(aAddr + (uint32_t)i * 2048u + ko));
#pragma unroll
                for (int jj = 0; jj < 2; jj++) {
                    uint32_t t[4];
                    ldsm_x4(t, bbase + SW128(bAddr + (uint32_t)jj * 2048u + ko));
                    bf[nxt][jj * 2][0] = t[0]; bf[nxt][jj * 2][1] = t[1];
                    bf[nxt][jj * 2 + 1][0] = t[2]; bf[nxt][jj * 2 + 1][1] = t[3];
                }
            }
#pragma unroll
            for (int i = 0; i < 4; i++)
#pragma unroll
                for (int j = 0; j < 4; j++)
                    mma16816(acc[i][j], af[cur][i], bf[cur][j]);
        }
    }

    // epilogue
    const int g = lane >> 2;
    const int tig = lane & 3;
#pragma unroll
    for (int i = 0; i < 4; i++) {
        const size_t r0 = m0 + wm * 64 + i * 16 + g;
#pragma unroll
        for (int j = 0; j < 4; j++) {
            const int col = (int)n0 + wn * 32 + j * 8 + tig * 2;
            const float2 bb = *(const float2*)(bias + col);
            const float v0 = acc[i][j][0] + bb.x, v1 = acc[i][j][1] + bb.y;
            const float v2 = acc[i][j][2] + bb.x, v3 = acc[i][j][3] + bb.y;
            if (Cf) {
                *(float2*)(Cf + r0 * N + col) = make_float2(v0, v1);
                *(float2*)(Cf + (r0 + 8) * N + col) = make_float2(v2, v3);
            } else {
                const float h0 = hround(v0), h1 = hround(v1);
                const float h2 = hround(v2), h3 = hround(v3);
                *(uint32_t*)(Ch + r0 * N + col) = pack2h(h0, h1);
                *(uint32_t*)(Cl + r0 * N + col) = pack2h(v0 - h0, v1 - h1);
                *(uint32_t*)(Ch + (r0 + 8) * N + col) = pack2h(h2, h3);
                *(uint32_t*)(Cl + (r0 + 8) * N + col) = pack2h(v2 - h2, v3 - h3);
            }
        }
    }
}

// ---------------------------------------------------------------------------
// Fused causal flash attention on tensor cores (fp16 split).
// grid (16 qtiles, 64 bh), 256 thr (8 warps), warp = 16 q-rows.
// S = 0.125*(Qh·Kh + Ql·Kh);  O += Ph·Vh + Pl·Vh.   (K,V quantized: err~2^-12)
// K/V double-buffered cp.async; one barrier per kt-iteration.
// smem: Qh,Ql 32KB + 2 x (Kh,Vh 16KB) = 64KB.
// ---------------------------------------------------------------------------
__global__ __launch_bounds__(256, 2) void attn_mma_kernel(
    const __half* __restrict__ qh_g, const __half* __restrict__ ql_g,
    __half* __restrict__ a2ctx)
{
    extern __shared__ char smA[];
    const uint32_t dyn = smem_to_u32(smA);
    const uint32_t sb = (dyn + 1023u) & ~1023u;
    char* p = smA + (sb - dyn);
    const uint32_t QH = sb, QL = sb + 16384u;

    const int tid = threadIdx.x;
    const int lane = tid & 31;
    const int w = tid >> 5;
    const int g = lane >> 2;
    const int tig = lane & 3;
    const int qt = blockIdx.x;
    const int bh = blockIdx.y;
    const int b = bh >> 4;
    const int hd = bh & 15;
    const int q0 = qt * 128;
    const int qw = q0 + w * 16;

    // K/V cp.async: tile = tid>>7 (0=Kh from +1024, 1=Vh from +2048), 2 thr/row
    const int kv_tile = tid >> 7;
    const int kv_r = (tid >> 1) & 63;
    const int kv_h = tid & 1;
    const __half* kv_src_base = qh_g + ((size_t)b * SEQ + kv_r) * 3072
        + (kv_tile ? 2048 : 1024) + hd * 64 + kv_h * 32;
    auto issue_kv = [&](int kt) {
        const uint32_t dst = sb + 32768u + (uint32_t)(kt & 1) * 16384u + (uint32_t)kv_tile * 8192u;
        const __half* src = kv_src_base + (size_t)kt * 64 * 3072;
#pragma unroll
        for (int c = 0; c < 4; c++)
            cp16(dst + SW128((uint32_t)(kv_r * 128 + kv_h * 64 + c * 16)), src + c * 8);
    };

    // Q tiles (hi, lo): 128 rows x 128B each (plain stores; covered by 1st barrier)
    {
        const int r = tid & 127;
        const int buf = tid >> 7;
        const __half* src = (buf ? ql_g : qh_g)
            + ((size_t)b * SEQ + q0 + r) * 3072 + hd * 64;
        char* dst = p + buf * 16384;
#pragma unroll
        for (int c = 0; c < 8; c++)
            *(uint4*)(dst + SW128((uint32_t)(r * 128 + c * 16))) = *(const uint4*)(src + c * 8);
    }

    issue_kv(0); cp_commit();

    float S[32], O[32];
#pragma unroll
    for (int i = 0; i < 32; i++) O[i] = 0.f;
    float m0 = -CUDART_INF_F, m1 = -CUDART_INF_F, l0 = 0.f, l1 = 0.f;

    const int ktmax = 2 * (qt + 1);
#pragma unroll 1
    for (int kt = 0; kt < ktmax; kt++) {
        const int k0 = kt * 64;
        cp_wait0();              // K/V stage kt resident
        __syncthreads();         // visible to all; all done with stage kt-1
        if (kt + 1 < ktmax) issue_kv(kt + 1);   // overlaps compute of kt
        cp_commit();

        const uint32_t kvb = sb + 32768u + (uint32_t)(kt & 1) * 16384u;
        const uint32_t KH = kvb, VH = kvb + 8192u;

        if (k0 <= qw + 15) {
#pragma unroll
            for (int i = 0; i < 32; i++) S[i] = 0.f;
            // ---- S = Qh·Kh + Ql·Kh
#pragma unroll
            for (int kat = 0; kat < 4; kat++) {
                const uint32_t swzA = SW128((uint32_t)((w * 16 + (lane & 15)) * 128
                                       + kat * 32 + ((lane >> 4) << 4)));
                uint32_t aqh[4], aql[4];
                ldsm_x4(aqh, QH + swzA);
                ldsm_x4(aql, QL + swzA);
#pragma unroll
                for (int j2 = 0; j2 < 4; j2++) {
                    const uint32_t swzB = SW128((uint32_t)((j2 * 16 + ((lane >> 4) & 1) * 8
                                            + (lane & 7)) * 128 + kat * 32 + ((lane >> 3) & 1) * 16));
                    uint32_t bkh[4];
                    ldsm_x4(bkh, KH + swzB);
                    mma16816(&S[(2 * j2) * 4], aqh, bkh);
                    mma16816(&S[(2 * j2 + 1) * 4], aqh, bkh + 2);
                    mma16816(&S[(2 * j2) * 4], aql, bkh);
                    mma16816(&S[(2 * j2 + 1) * 4], aql, bkh + 2);
                }
            }
            // ---- scale + causal mask + online softmax
            const int row0 = qw + g, row1 = row0 + 8;
            const bool msk = (k0 + 63 > qw);
            float tm0 = -CUDART_INF_F, tm1 = -CUDART_INF_F;
#pragma unroll
            for (int j = 0; j < 8; j++) {
                float* sj = &S[j * 4];
                sj[0] *= 0.125f; sj[1] *= 0.125f; sj[2] *= 0.125f; sj[3] *= 0.125f;
                if (msk) {
                    const int c0 = k0 + j * 8 + 2 * tig;
                    if (c0 > row0)     sj[0] = -CUDART_INF_F;
                    if (c0 + 1 > row0) sj[1] = -CUDART_INF_F;
                    if (c0 > row1)     sj[2] = -CUDART_INF_F;
                    if (c0 + 1 > row1) sj[3] = -CUDART_INF_F;
                }
                tm0 = fmaxf(tm0, fmaxf(sj[0], sj[1]));
                tm1 = fmaxf(tm1, fmaxf(sj[2], sj[3]));
            }
            tm0 = fmaxf(tm0, __shfl_xor_sync(0xffffffffu, tm0, 1));
            tm0 = fmaxf(tm0, __shfl_xor_sync(0xffffffffu, tm0, 2));
            tm1 = fmaxf(tm1, __shfl_xor_sync(0xffffffffu, tm1, 1));
            tm1 = fmaxf(tm1, __shfl_xor_sync(0xffffffffu, tm1, 2));
            const float mn0 = fmaxf(m0, tm0), mn1 = fmaxf(m1, tm1);
            const float corr0 = __expf(m0 - mn0), corr1 = __expf(m1 - mn1);
            m0 = mn0; m1 = mn1;

            float ls0 = 0.f, ls1 = 0.f;
            uint32_t PHf[16], PLf[16];
#pragma unroll
            for (int j = 0; j < 8; j++) {
                const float e0 = __expf(S[j * 4 + 0] - mn0);
                const float e1 = __expf(S[j * 4 + 1] - mn0);
                const float e2 = __expf(S[j * 4 + 2] - mn1);
                const float e3 = __expf(S[j * 4 + 3] - mn1);
                ls0 += e0 + e1; ls1 += e2 + e3;
                const float h0 = hround(e0), h1 = hround(e1);
                const float h2 = hround(e2), h3 = hround(e3);
                PHf[j * 2 + 0] = pack2h(h0, h1);
                PHf[j * 2 + 1] = pack2h(h2, h3);
                PLf[j * 2 + 0] = pack2h(e0 - h0, e1 - h1);
                PLf[j * 2 + 1] = pack2h(e2 - h2, e3 - h3);
            }
            ls0 += __shfl_xor_sync(0xffffffffu, ls0, 1);
            ls0 += __shfl_xor_sync(0xffffffffu, ls0, 2);
            ls1 += __shfl_xor_sync(0xffffffffu, ls1, 1);
            ls1 += __shfl_xor_sync(0xffffffffu, ls1, 2);
            l0 = l0 * corr0 + ls0;
            l1 = l1 * corr1 + ls1;
#pragma unroll
            for (int j = 0; j < 8; j++) {
                O[j * 4 + 0] *= corr0; O[j * 4 + 1] *= corr0;
                O[j * 4 + 2] *= corr1; O[j * 4 + 3] *= corr1;
            }
            // ---- O += Ph·Vh + Pl·Vh   (V^T via ldmatrix.trans)
#pragma unroll
            for (int kat = 0; kat < 4; kat++) {
#pragma unroll
                for (int jd2 = 0; jd2 < 4; jd2++) {
                    const uint32_t swzV = SW128((uint32_t)((kat * 16 + ((lane >> 3) & 1) * 8
                                            + (lane & 7)) * 128 + jd2 * 32 + ((lane >> 4) & 1) * 16));
                    uint32_t bvh[4];
                    ldsm_x4_t(bvh, VH + swzV);
                    mma16816(&O[(2 * jd2) * 4], &PHf[4 * kat], bvh);
                    mma16816(&O[(2 * jd2 + 1) * 4], &PHf[4 * kat], bvh + 2);
                    mma16816(&O[(2 * jd2) * 4], &PLf[4 * kat], bvh);
                    mma16816(&O[(2 * jd2 + 1) * 4], &PLf[4 * kat], bvh + 2);
                }
            }
        }
    }

    // epilogue: normalized O -> split ctx rows [hi | lo] (width 2048)
    const float inv0 = 1.f / l0, inv1 = 1.f / l1;
    __half* rp0 = a2ctx + ((size_t)b * SEQ + qw + g) * K2 + hd * 64;
    __half* rp1 = rp0 + (size_t)8 * K2;
#pragma unroll
    for (int j = 0; j < 8; j++) {
        const int c = j * 8 + 2 * tig;
        {
            const float v0 = O[j * 4 + 0] * inv0, v1 = O[j * 4 + 1] * inv0;
            const float h0 = hround(v0), h1 = hround(v1);
            *(uint32_t*)(rp0 + c) = pack2h(h0, h1);
            *(uint32_t*)(rp0 + 1024 + c) = pack2h(v0 - h0, v1 - h1);
        }
        {
            const float v2 = O[j * 4 + 2] * inv1, v3 = O[j * 4 + 3] * inv1;
            const float h2 = hround(v2), h3 = hround(v3);
            *(uint32_t*)(rp1 + c) = pack2h(h2, h3);
            *(uint32_t*)(rp1 + 1024 + c) = pack2h(v2 - h2, v3 - h3);
        }
    }
}

// ---------------------------------------------------------------------------
extern "C" void kernel_launch(void* const* d_in, const int* in_sizes, int n_in,
                              void* d_out, int out_size)
{
    (void)in_sizes; (void)n_in; (void)out_size;
    const float* x     = (const float*)d_in[0];
    const float* W_qkv = (const float*)d_in[2];
    const float* b_qkv = (const float*)d_in[3];
    const float* W_out = (const float*)d_in[4];
    const float* b_out = (const float*)d_in[5];
    float* out = (float*)d_out;

    __half *a2x, *w2qkv, *a2ctx, *w2out, *qh, *ql;
    cudaGetSymbolAddress((void**)&a2x, g_a2x);
    cudaGetSymbolAddress((void**)&w2qkv, g_w2qkv);
    cudaGetSymbolAddress((void**)&a2ctx, g_a2ctx);
    cudaGetSymbolAddress((void**)&w2out, g_w2out);
    cudaGetSymbolAddress((void**)&qh, g_qh);
    cudaGetSymbolAddress((void**)&ql, g_ql);

    const int gsmem = 97 * 1024;   // 3x32KB ring + align
    const int asmem = 66 * 1024;   // 32KB Q + 2x16KB KV + align
    cudaFuncSetAttribute(gemm_mma_kernel, cudaFuncAttributeMaxDynamicSharedMemorySize, gsmem);
    cudaFuncSetAttribute(gemm_mma_kernel, cudaFuncAttributePreferredSharedMemoryCarveout, 100);
    cudaFuncSetAttribute(attn_mma_kernel, cudaFuncAttributeMaxDynamicSharedMemorySize, asmem);
    cudaFuncSetAttribute(attn_mma_kernel, cudaFuncAttributePreferredSharedMemoryCarveout, 100);

    // 0) split-precision conversions (fp16 hi/lo)
    split_kernel<<<(BT * HID / 4 + 255) / 256, 256>>>(x, a2x, HID, (size_t)BT * HID / 4, 0);
    split_kernel<<<(3 * HID * HID / 4 + 255) / 256, 256>>>(W_qkv, w2qkv, HID, (size_t)3 * HID * HID / 4, 1);
    split_kernel<<<(HID * HID / 4 + 255) / 256, 256>>>(W_out, w2out, HID, (size_t)HID * HID / 4, 1);

    // 1) QKV projection (HMMA fp16): [8192,2048] x [3072,2048]^T -> hi/lo fp16
    gemm_mma_kernel<<<dim3(3 * HID / 128, BT / 128), 256, gsmem>>>(
        a2x, w2qkv, b_qkv, nullptr, qh, ql, 3 * HID);

    // 2) fused causal attention (HMMA fp16 split) -> split-fp16 ctx
    attn_mma_kernel<<<dim3(SEQ / 128, 4 * NHEADS), 256, asmem>>>(qh, ql, a2ctx);

    // 3) output projection (HMMA fp16): [8192,2048] x [1024,2048]^T -> fp32 out
    gemm_mma_kernel<<<dim3(HID / 128, BT / 128), 256, gsmem>>>(
        a2ctx, w2out, b_out, out, nullptr, nullptr, HID);
}

// round 13
// speedup vs baseline: 1.3003x; 1.2354x over previous
#include <cuda_runtime.h>
#include <cuda_fp16.h>
#include <math_constants.h>
#include <cstdint>

#define HID 1024
#define NHEADS 16
#define HDIM 64
#define SEQ 2048
#define BT 8192
#define K2 2048            // ctx split width for GEMM2 (fp16 hi/lo)

// ---------------------------------------------------------------------------
// Scratch (__device__ globals: runtime allocation is forbidden)
// ---------------------------------------------------------------------------
__device__ __half g_xh[(size_t)BT * HID];          // x hi (fp16)
__device__ __half g_wqkv[(size_t)3 * HID * HID];   // W_qkv hi (fp16)
__device__ __half g_a2ctx[(size_t)BT * K2];        // [ctx_h|ctx_l]
__device__ __half g_w2out[(size_t)HID * K2];       // [Wh|Wh] of W_out
__device__ __half g_qh[(size_t)BT * 3 * HID];      // qkv hi (fp16)
__device__ __half g_ql[(size_t)BT * 3 * HID];      // qkv lo (fp16)

// ---------------------------------------------------------------------------
// helpers
// ---------------------------------------------------------------------------
__device__ __forceinline__ uint32_t smem_to_u32(const void* p) {
    uint32_t a;
    asm("{ .reg .u64 t; cvta.to.shared.u64 t, %1; cvt.u32.u64 %0, t; }"
        : "=r"(a) : "l"(p));
    return a;
}
#define SW128(b) ((b) ^ (((b) >> 3) & 0x70u))

__device__ __forceinline__ void ldsm_x4(uint32_t* r, uint32_t addr) {
    asm volatile("ldmatrix.sync.aligned.m8n8.x4.shared.b16 {%0,%1,%2,%3}, [%4];"
        : "=r"(r[0]), "=r"(r[1]), "=r"(r[2]), "=r"(r[3]) : "r"(addr));
}
__device__ __forceinline__ void ldsm_x4_t(uint32_t* r, uint32_t addr) {
    asm volatile("ldmatrix.sync.aligned.m8n8.x4.trans.shared.b16 {%0,%1,%2,%3}, [%4];"
        : "=r"(r[0]), "=r"(r[1]), "=r"(r[2]), "=r"(r[3]) : "r"(addr));
}
__device__ __forceinline__ void mma16816(float* d, const uint32_t* a, const uint32_t* b) {
    asm volatile("mma.sync.aligned.m16n8k16.row.col.f32.f16.f16.f32 "
        "{%0,%1,%2,%3}, {%4,%5,%6,%7}, {%8,%9}, {%0,%1,%2,%3};"
        : "+f"(d[0]), "+f"(d[1]), "+f"(d[2]), "+f"(d[3])
        : "r"(a[0]), "r"(a[1]), "r"(a[2]), "r"(a[3]), "r"(b[0]), "r"(b[1]));
}
__device__ __forceinline__ void cp16(uint32_t dst, const void* src) {
    asm volatile("cp.async.cg.shared.global [%0], [%1], 16;" :: "r"(dst), "l"(src));
}
__device__ __forceinline__ void cp_commit() { asm volatile("cp.async.commit_group;" ::: "memory"); }
__device__ __forceinline__ void cp_wait1()  { asm volatile("cp.async.wait_group 1;" ::: "memory"); }
__device__ __forceinline__ void cp_wait0()  { asm volatile("cp.async.wait_group 0;" ::: "memory"); }

__device__ __forceinline__ uint32_t pack2h(float a, float b) {
    __half2 t = __floats2half2_rn(a, b);
    return *reinterpret_cast<uint32_t*>(&t);
}
__device__ __forceinline__ float hround(float v) {
    return __half2float(__float2half_rn(v));
}

// ---------------------------------------------------------------------------
// Convert: src fp32 [rows, K] -> fp16.
//   dup=0: dst [rows, K]  = hi
//   dup=1: dst [rows, 2K] = [hi | hi]
// ---------------------------------------------------------------------------
__global__ __launch_bounds__(256) void conv_kernel(
    const float* __restrict__ src, __half* __restrict__ dst,
    int K, size_t total4, int dup)
{
    size_t idx = (size_t)blockIdx.x * blockDim.x + threadIdx.x;
    if (idx >= total4) return;
    int kq = K >> 2;
    size_t r = idx / kq;
    int c = (int)(idx % kq) << 2;
    float4 v = *(const float4*)(src + r * K + c);
    uint2 hi = make_uint2(pack2h(hround(v.x), hround(v.y)),
                          pack2h(hround(v.z), hround(v.w)));
    if (dup) {
        __half* drow = dst + r * (size_t)(2 * K);
        *(uint2*)(drow + c) = hi;
        *(uint2*)(drow + K + c) = hi;
    } else {
        *(uint2*)(dst + r * K + c) = hi;
    }
}

// ---------------------------------------------------------------------------
// mma.sync fp16 GEMM: C[M,N] = A[M,K] @ W[N,K]^T + bias   (K runtime, %64==0)
// CTA 128x128, BK=64, 256 thr (8 warps 2x4), warp tile 64x32.
// 3-stage cp.async ring, one barrier per k-step.
// Epilogue: fp32 (Cf) or fp16 hi/lo split (Ch/Cl).
// ---------------------------------------------------------------------------
__global__ __launch_bounds__(256, 2) void gemm_mma_kernel(
    const __half* __restrict__ A2, const __half* __restrict__ W2,
    const float* __restrict__ bias, float* __restrict__ Cf,
    __half* __restrict__ Ch, __half* __restrict__ Cl, int N, int K)
{
    extern __shared__ char dsm[];
    const uint32_t dyn = smem_to_u32(dsm);
    const uint32_t base = (dyn + 1023u) & ~1023u;

    const int tid = threadIdx.x;
    const int lane = tid & 31;
    const int wid = tid >> 5;
    const int wm = wid >> 2;
    const int wn = wid & 3;
    const size_t m0 = (size_t)blockIdx.y * 128;
    const size_t n0 = (size_t)blockIdx.x * 128;
    const int ksteps = K >> 6;

    const int arow = tid >> 1;
    const int ahalf = tid & 1;
    const __half* gA = A2 + (m0 + arow) * (size_t)K + ahalf * 32;
    const __half* gB = W2 + (n0 + arow) * (size_t)K + ahalf * 32;
    const uint32_t sts = (uint32_t)(arow * 128 + ahalf * 64);

    float acc[4][4][4];
#pragma unroll
    for (int i = 0; i < 4; i++)
#pragma unroll
        for (int j = 0; j < 4; j++)
#pragma unroll
            for (int r = 0; r < 4; r++) acc[i][j][r] = 0.f;

    auto issue = [&](int s) {
        const uint32_t ab = base + (uint32_t)(s % 3) * 32768u;
        const int k0 = s * 64;
#pragma unroll
        for (int c = 0; c < 4; c++) {
            const uint32_t sw = SW128(sts + (uint32_t)c * 16u);
            cp16(ab + sw, gA + k0 + c * 8);
            cp16(ab + 16384u + sw, gB + k0 + c * 8);
        }
    };

    issue(0); cp_commit();
    issue(1); cp_commit();

#pragma unroll 1
    for (int s = 0; s < ksteps; s++) {
        cp_wait1();              // stage s resident (stage s+1 may be pending)
        __syncthreads();         // all warps see stage s; all done with stage s-1
        if (s + 2 < ksteps) issue(s + 2);   // ring distance 2
        cp_commit();

        const uint32_t abase = base + (uint32_t)(s % 3) * 32768u;
        const uint32_t bbase = abase + 16384u;
#pragma unroll
        for (int kat = 0; kat < 4; kat++) {
            uint32_t af[4][4], bf[4][2];
#pragma unroll
            for (int i = 0; i < 4; i++) {
                uint32_t row = (uint32_t)(wm * 64 + i * 16 + (lane & 15));
                uint32_t byte = row * 128u + (uint32_t)kat * 32u + ((lane >> 4) << 4);
                ldsm_x4(af[i], abase + SW128(byte));
            }
#pragma unroll
            for (int jj = 0; jj < 2; jj++) {
                uint32_t row = (uint32_t)(wn * 32 + jj * 16 + ((lane >> 4) & 1) * 8 + (lane & 7));
                uint32_t byte = row * 128u + (uint32_t)kat * 32u + (((lane >> 3) & 1) << 4);
                uint32_t t[4];
                ldsm_x4(t, bbase + SW128(byte));
                bf[jj * 2][0] = t[0]; bf[jj * 2][1] = t[1];
                bf[jj * 2 + 1][0] = t[2]; bf[jj * 2 + 1][1] = t[3];
            }
#pragma unroll
            for (int i = 0; i < 4; i++)
#pragma unroll
                for (int j = 0; j < 4; j++)
                    mma16816(acc[i][j], af[i], bf[j]);
        }
    }

    // epilogue
    const int g = lane >> 2;
    const int tig = lane & 3;
#pragma unroll
    for (int i = 0; i < 4; i++) {
        const size_t r0 = m0 + wm * 64 + i * 16 + g;
#pragma unroll
        for (int j = 0; j < 4; j++) {
            const int col = (int)n0 + wn * 32 + j * 8 + tig * 2;
            const float2 bb = *(const float2*)(bias + col);
            const float v0 = acc[i][j][0] + bb.x, v1 = acc[i][j][1] + bb.y;
            const float v2 = acc[i][j][2] + bb.x, v3 = acc[i][j][3] + bb.y;
            if (Cf) {
                *(float2*)(Cf + r0 * N + col) = make_float2(v0, v1);
                *(float2*)(Cf + (r0 + 8) * N + col) = make_float2(v2, v3);
            } else {
                const float h0 = hround(v0), h1 = hround(v1);
                const float h2 = hround(v2), h3 = hround(v3);
                *(uint32_t*)(Ch + r0 * N + col) = pack2h(h0, h1);
                *(uint32_t*)(Cl + r0 * N + col) = pack2h(v0 - h0, v1 - h1);
                *(uint32_t*)(Ch + (r0 + 8) * N + col) = pack2h(h2, h3);
                *(uint32_t*)(Cl + (r0 + 8) * N + col) = pack2h(v2 - h2, v3 - h3);
            }
        }
    }
}

// ---------------------------------------------------------------------------
// Fused causal flash attention on tensor cores (fp16 split).
// grid (16 qtiles, 64 bh), 256 thr (8 warps), warp = 16 q-rows.
// S = 0.125*(Qh·Kh + Ql·Kh);  O += Ph·Vh + Pl·Vh.   (K,V quantized: err~2^-12)
// K/V double-buffered cp.async; one barrier per kt-iteration.
// smem: Qh,Ql 32KB + 2 x (Kh,Vh 16KB) = 64KB.
// ---------------------------------------------------------------------------
__global__ __launch_bounds__(256, 2) void attn_mma_kernel(
    const __half* __restrict__ qh_g, const __half* __restrict__ ql_g,
    __half* __restrict__ a2ctx)
{
    extern __shared__ char smA[];
    const uint32_t dyn = smem_to_u32(smA);
    const uint32_t sb = (dyn + 1023u) & ~1023u;
    char* p = smA + (sb - dyn);
    const uint32_t QH = sb, QL = sb + 16384u;

    const int tid = threadIdx.x;
    const int lane = tid & 31;
    const int w = tid >> 5;
    const int g = lane >> 2;
    const int tig = lane & 3;
    const int qt = blockIdx.x;
    const int bh = blockIdx.y;
    const int b = bh >> 4;
    const int hd = bh & 15;
    const int q0 = qt * 128;
    const int qw = q0 + w * 16;

    // K/V cp.async: tile = tid>>7 (0=Kh from +1024, 1=Vh from +2048), 2 thr/row
    const int kv_tile = tid >> 7;
    const int kv_r = (tid >> 1) & 63;
    const int kv_h = tid & 1;
    const __half* kv_src_base = qh_g + ((size_t)b * SEQ + kv_r) * 3072
        + (kv_tile ? 2048 : 1024) + hd * 64 + kv_h * 32;
    auto issue_kv = [&](int kt) {
        const uint32_t dst = sb + 32768u + (uint32_t)(kt & 1) * 16384u + (uint32_t)kv_tile * 8192u;
        const __half* src = kv_src_base + (size_t)kt * 64 * 3072;
#pragma unroll
        for (int c = 0; c < 4; c++)
            cp16(dst + SW128((uint32_t)(kv_r * 128 + kv_h * 64 + c * 16)), src + c * 8);
    };

    // Q tiles (hi, lo): 128 rows x 128B each (plain stores; covered by 1st barrier)
    {
        const int r = tid & 127;
        const int buf = tid >> 7;
        const __half* src = (buf ? ql_g : qh_g)
            + ((size_t)b * SEQ + q0 + r) * 3072 + hd * 64;
        char* dst = p + buf * 16384;
#pragma unroll
        for (int c = 0; c < 8; c++)
            *(uint4*)(dst + SW128((uint32_t)(r * 128 + c * 16))) = *(const uint4*)(src + c * 8);
    }

    issue_kv(0); cp_commit();

    float S[32], O[32];
#pragma unroll
    for (int i = 0; i < 32; i++) O[i] = 0.f;
    float m0 = -CUDART_INF_F, m1 = -CUDART_INF_F, l0 = 0.f, l1 = 0.f;

    const int ktmax = 2 * (qt + 1);
#pragma unroll 1
    for (int kt = 0; kt < ktmax; kt++) {
        const int k0 = kt * 64;
        cp_wait0();              // K/V stage kt resident
        __syncthreads();         // visible to all; all done with stage kt-1
        if (kt + 1 < ktmax) issue_kv(kt + 1);   // overlaps compute of kt
        cp_commit();

        const uint32_t kvb = sb + 32768u + (uint32_t)(kt & 1) * 16384u;
        const uint32_t KH = kvb, VH = kvb + 8192u;

        if (k0 <= qw + 15) {
#pragma unroll
            for (int i = 0; i < 32; i++) S[i] = 0.f;
            // ---- S = Qh·Kh + Ql·Kh
#pragma unroll
            for (int kat = 0; kat < 4; kat++) {
                const uint32_t swzA = SW128((uint32_t)((w * 16 + (lane & 15)) * 128
                                       + kat * 32 + ((lane >> 4) << 4)));
                uint32_t aqh[4], aql[4];
                ldsm_x4(aqh, QH + swzA);
                ldsm_x4(aql, QL + swzA);
#pragma unroll
                for (int j2 = 0; j2 < 4; j2++) {
                    const uint32_t swzB = SW128((uint32_t)((j2 * 16 + ((lane >> 4) & 1) * 8
                                            + (lane & 7)) * 128 + kat * 32 + ((lane >> 3) & 1) * 16));
                    uint32_t bkh[4];
                    ldsm_x4(bkh, KH + swzB);
                    mma16816(&S[(2 * j2) * 4], aqh, bkh);
                    mma16816(&S[(2 * j2 + 1) * 4], aqh, bkh + 2);
                    mma16816(&S[(2 * j2) * 4], aql, bkh);
                    mma16816(&S[(2 * j2 + 1) * 4], aql, bkh + 2);
                }
            }
            // ---- scale + causal mask + online softmax
            const int row0 = qw + g, row1 = row0 + 8;
            const bool msk = (k0 + 63 > qw);
            float tm0 = -CUDART_INF_F, tm1 = -CUDART_INF_F;
#pragma unroll
            for (int j = 0; j < 8; j++) {
                float* sj = &S[j * 4];
                sj[0] *= 0.125f; sj[1] *= 0.125f; sj[2] *= 0.125f; sj[3] *= 0.125f;
                if (msk) {
                    const int c0 = k0 + j * 8 + 2 * tig;
                    if (c0 > row0)     sj[0] = -CUDART_INF_F;
                    if (c0 + 1 > row0) sj[1] = -CUDART_INF_F;
                    if (c0 > row1)     sj[2] = -CUDART_INF_F;
                    if (c0 + 1 > row1) sj[3] = -CUDART_INF_F;
                }
                tm0 = fmaxf(tm0, fmaxf(sj[0], sj[1]));
                tm1 = fmaxf(tm1, fmaxf(sj[2], sj[3]));
            }
            tm0 = fmaxf(tm0, __shfl_xor_sync(0xffffffffu, tm0, 1));
            tm0 = fmaxf(tm0, __shfl_xor_sync(0xffffffffu, tm0, 2));
            tm1 = fmaxf(tm1, __shfl_xor_sync(0xffffffffu, tm1, 1));
            tm1 = fmaxf(tm1, __shfl_xor_sync(0xffffffffu, tm1, 2));
            const float mn0 = fmaxf(m0, tm0), mn1 = fmaxf(m1, tm1);
            const float corr0 = __expf(m0 - mn0), corr1 = __expf(m1 - mn1);
            m0 = mn0; m1 = mn1;

            float ls0 = 0.f, ls1 = 0.f;
            uint32_t PHf[16], PLf[16];
#pragma unroll
            for (int j = 0; j < 8; j++) {
                const float e0 = __expf(S[j * 4 + 0] - mn0);
                const float e1 = __expf(S[j * 4 + 1] - mn0);
                const float e2 = __expf(S[j * 4 + 2] - mn1);
                const float e3 = __expf(S[j * 4 + 3] - mn1);
                ls0 += e0 + e1; ls1 += e2 + e3;
                const float h0 = hround(e0), h1 = hround(e1);
                const float h2 = hround(e2), h3 = hround(e3);
                PHf[j * 2 + 0] = pack2h(h0, h1);
                PHf[j * 2 + 1] = pack2h(h2, h3);
                PLf[j * 2 + 0] = pack2h(e0 - h0, e1 - h1);
                PLf[j * 2 + 1] = pack2h(e2 - h2, e3 - h3);
            }
            ls0 += __shfl_xor_sync(0xffffffffu, ls0, 1);
            ls0 += __shfl_xor_sync(0xffffffffu, ls0, 2);
            ls1 += __shfl_xor_sync(0xffffffffu, ls1, 1);
            ls1 += __shfl_xor_sync(0xffffffffu, ls1, 2);
            l0 = l0 * corr0 + ls0;
            l1 = l1 * corr1 + ls1;
#pragma unroll
            for (int j = 0; j < 8; j++) {
                O[j * 4 + 0] *= corr0; O[j * 4 + 1] *= corr0;
                O[j * 4 + 2] *= corr1; O[j * 4 + 3] *= corr1;
            }
            // ---- O += Ph·Vh + Pl·Vh   (V^T via ldmatrix.trans)
#pragma unroll
            for (int kat = 0; kat < 4; kat++) {
#pragma unroll
                for (int jd2 = 0; jd2 < 4; jd2++) {
                    const uint32_t swzV = SW128((uint32_t)((kat * 16 + ((lane >> 3) & 1) * 8
                                            + (lane & 7)) * 128 + jd2 * 32 + ((lane >> 4) & 1) * 16));
                    uint32_t bvh[4];
                    ldsm_x4_t(bvh, VH + swzV);
                    mma16816(&O[(2 * jd2) * 4], &PHf[4 * kat], bvh);
                    mma16816(&O[(2 * jd2 + 1) * 4], &PHf[4 * kat], bvh + 2);
                    mma16816(&O[(2 * jd2) * 4], &PLf[4 * kat], bvh);
                    mma16816(&O[(2 * jd2 + 1) * 4], &PLf[4 * kat], bvh + 2);
                }
            }
        }
    }

    // epilogue: normalized O -> split ctx rows [hi | lo] (width 2048)
    const float inv0 = 1.f / l0, inv1 = 1.f / l1;
    __half* rp0 = a2ctx + ((size_t)b * SEQ + qw + g) * K2 + hd * 64;
    __half* rp1 = rp0 + (size_t)8 * K2;
#pragma unroll
    for (int j = 0; j < 8; j++) {
        const int c = j * 8 + 2 * tig;
        {
            const float v0 = O[j * 4 + 0] * inv0, v1 = O[j * 4 + 1] * inv0;
            const float h0 = hround(v0), h1 = hround(v1);
            *(uint32_t*)(rp0 + c) = pack2h(h0, h1);
            *(uint32_t*)(rp0 + 1024 + c) = pack2h(v0 - h0, v1 - h1);
        }
        {
            const float v2 = O[j * 4 + 2] * inv1, v3 = O[j * 4 + 3] * inv1;
            const float h2 = hround(v2), h3 = hround(v3);
            *(uint32_t*)(rp1 + c) = pack2h(h2, h3);
            *(uint32_t*)(rp1 + 1024 + c) = pack2h(v2 - h2, v3 - h3);
        }
    }
}

// ---------------------------------------------------------------------------
extern "C" void kernel_launch(void* const* d_in, const int* in_sizes, int n_in,
                              void* d_out, int out_size)
{
    (void)in_sizes; (void)n_in; (void)out_size;
    const float* x     = (const float*)d_in[0];
    const float* W_qkv = (const float*)d_in[2];
    const float* b_qkv = (const float*)d_in[3];
    const float* W_out = (const float*)d_in[4];
    const float* b_out = (const float*)d_in[5];
    float* out = (float*)d_out;

    __half *xh, *wqkv, *a2ctx, *w2out, *qh, *ql;
    cudaGetSymbolAddress((void**)&xh, g_xh);
    cudaGetSymbolAddress((void**)&wqkv, g_wqkv);
    cudaGetSymbolAddress((void**)&a2ctx, g_a2ctx);
    cudaGetSymbolAddress((void**)&w2out, g_w2out);
    cudaGetSymbolAddress((void**)&qh, g_qh);
    cudaGetSymbolAddress((void**)&ql, g_ql);

    const int gsmem = 97 * 1024;   // 3x32KB ring + align
    const int asmem = 66 * 1024;   // 32KB Q + 2x16KB KV + align
    cudaFuncSetAttribute(gemm_mma_kernel, cudaFuncAttributeMaxDynamicSharedMemorySize, gsmem);
    cudaFuncSetAttribute(gemm_mma_kernel, cudaFuncAttributePreferredSharedMemoryCarveout, 100);
    cudaFuncSetAttribute(attn_mma_kernel, cudaFuncAttributeMaxDynamicSharedMemorySize, asmem);
    cudaFuncSetAttribute(attn_mma_kernel, cudaFuncAttributePreferredSharedMemoryCarveout, 100);

    // 0) fp32 -> fp16 conversions
    conv_kernel<<<(BT * HID / 4 + 255) / 256, 256>>>(x, xh, HID, (size_t)BT * HID / 4, 0);
    conv_kernel<<<(3 * HID * HID / 4 + 255) / 256, 256>>>(W_qkv, wqkv, HID, (size_t)3 * HID * HID / 4, 0);
    conv_kernel<<<(HID * HID / 4 + 255) / 256, 256>>>(W_out, w2out, HID, (size_t)HID * HID / 4, 1);

    // 1) QKV projection (HMMA fp16, K=1024): [8192,1024] x [3072,1024]^T -> hi/lo
    gemm_mma_kernel<<<dim3(3 * HID / 128, BT / 128), 256, gsmem>>>(
        xh, wqkv, b_qkv, nullptr, qh, ql, 3 * HID, HID);

    // 2) fused causal attention (HMMA fp16 split) -> split-fp16 ctx
    attn_mma_kernel<<<dim3(SEQ / 128, 4 * NHEADS), 256, asmem>>>(qh, ql, a2ctx);

    // 3) output projection (HMMA fp16, K=2048): exact ctx hi/lo -> fp32 out
    gemm_mma_kernel<<<dim3(HID / 128, BT / 128), 256, gsmem>>>(
        a2ctx, w2out, b_out, out, nullptr, nullptr, HID, K2);
}

// round 14
// speedup vs baseline: 1.5879x; 1.2212x over previous
#include <cuda_runtime.h>
#include <cuda_fp16.h>
#include <math_constants.h>
#include <cstdint>

#define HID 1024
#define NHEADS 16
#define HDIM 64
#define SEQ 2048
#define BT 8192
#define K2 2048            // ctx split width for GEMM2 (fp16 hi/lo)

// ---------------------------------------------------------------------------
// Scratch (__device__ globals: runtime allocation is forbidden)
// ---------------------------------------------------------------------------
__device__ __half g_xh[(size_t)BT * HID];          // x hi (fp16)
__device__ __half g_wqkv[(size_t)3 * HID * HID];   // W_qkv hi (fp16)
__device__ __half g_a2ctx[(size_t)BT * K2];        // [ctx_h|ctx_l]
__device__ __half g_w2out[(size_t)HID * K2];       // [Wh|Wh] of W_out
__device__ __half g_qh[(size_t)BT * 3 * HID];      // qkv hi (fp16)

// ---------------------------------------------------------------------------
// helpers
// ---------------------------------------------------------------------------
__device__ __forceinline__ uint32_t smem_to_u32(const void* p) {
    uint32_t a;
    asm("{ .reg .u64 t; cvta.to.shared.u64 t, %1; cvt.u32.u64 %0, t; }"
        : "=r"(a) : "l"(p));
    return a;
}
#define SW128(b) ((b) ^ (((b) >> 3) & 0x70u))

__device__ __forceinline__ void ldsm_x4(uint32_t* r, uint32_t addr) {
    asm volatile("ldmatrix.sync.aligned.m8n8.x4.shared.b16 {%0,%1,%2,%3}, [%4];"
        : "=r"(r[0]), "=r"(r[1]), "=r"(r[2]), "=r"(r[3]) : "r"(addr));
}
__device__ __forceinline__ void ldsm_x4_t(uint32_t* r, uint32_t addr) {
    asm volatile("ldmatrix.sync.aligned.m8n8.x4.trans.shared.b16 {%0,%1,%2,%3}, [%4];"
        : "=r"(r[0]), "=r"(r[1]), "=r"(r[2]), "=r"(r[3]) : "r"(addr));
}
__device__ __forceinline__ void mma16816(float* d, const uint32_t* a, const uint32_t* b) {
    asm volatile("mma.sync.aligned.m16n8k16.row.col.f32.f16.f16.f32 "
        "{%0,%1,%2,%3}, {%4,%5,%6,%7}, {%8,%9}, {%0,%1,%2,%3};"
        : "+f"(d[0]), "+f"(d[1]), "+f"(d[2]), "+f"(d[3])
        : "r"(a[0]), "r"(a[1]), "r"(a[2]), "r"(a[3]), "r"(b[0]), "r"(b[1]));
}
__device__ __forceinline__ void cp16(uint32_t dst, const void* src) {
    asm volatile("cp.async.cg.shared.global [%0], [%1], 16;" :: "r"(dst), "l"(src));
}
__device__ __forceinline__ void cp_commit() { asm volatile("cp.async.commit_group;" ::: "memory"); }
__device__ __forceinline__ void cp_wait1()  { asm volatile("cp.async.wait_group 1;" ::: "memory"); }
__device__ __forceinline__ void cp_wait0()  { asm volatile("cp.async.wait_group 0;" ::: "memory"); }

__device__ __forceinline__ uint32_t pack2h(float a, float b) {
    __half2 t = __floats2half2_rn(a, b);
    return *reinterpret_cast<uint32_t*>(&t);
}
__device__ __forceinline__ float hround(float v) {
    return __half2float(__float2half_rn(v));
}

// ---------------------------------------------------------------------------
// Convert: src fp32 [rows, K] -> fp16.
//   dup=0: dst [rows, K]  = hi
//   dup=1: dst [rows, 2K] = [hi | hi]
// ---------------------------------------------------------------------------
__global__ __launch_bounds__(256) void conv_kernel(
    const float* __restrict__ src, __half* __restrict__ dst,
    int K, size_t total4, int dup)
{
    size_t idx = (size_t)blockIdx.x * blockDim.x + threadIdx.x;
    if (idx >= total4) return;
    int kq = K >> 2;
    size_t r = idx / kq;
    int c = (int)(idx % kq) << 2;
    float4 v = *(const float4*)(src + r * K + c);
    uint2 hi = make_uint2(pack2h(hround(v.x), hround(v.y)),
                          pack2h(hround(v.z), hround(v.w)));
    if (dup) {
        __half* drow = dst + r * (size_t)(2 * K);
        *(uint2*)(drow + c) = hi;
        *(uint2*)(drow + K + c) = hi;
    } else {
        *(uint2*)(dst + r * K + c) = hi;
    }
}

// ---------------------------------------------------------------------------
// mma.sync fp16 GEMM: C[M,N] = A[M,K] @ W[N,K]^T + bias   (K runtime, %64==0)
// CTA 128x128, BK=64, 256 thr (8 warps 2x4), warp tile 64x32.
// 3-stage cp.async ring, one barrier per k-step.
// Epilogue: fp32 (Cf), or fp16 hi/lo split (Ch+Cl), or fp16 hi only (Ch).
// ---------------------------------------------------------------------------
__global__ __launch_bounds__(256, 2) void gemm_mma_kernel(
    const __half* __restrict__ A2, const __half* __restrict__ W2,
    const float* __restrict__ bias, float* __restrict__ Cf,
    __half* __restrict__ Ch, __half* __restrict__ Cl, int N, int K)
{
    extern __shared__ char dsm[];
    const uint32_t dyn = smem_to_u32(dsm);
    const uint32_t base = (dyn + 1023u) & ~1023u;

    const int tid = threadIdx.x;
    const int lane = tid & 31;
    const int wid = tid >> 5;
    const int wm = wid >> 2;
    const int wn = wid & 3;
    const size_t m0 = (size_t)blockIdx.y * 128;
    const size_t n0 = (size_t)blockIdx.x * 128;
    const int ksteps = K >> 6;

    const int arow = tid >> 1;
    const int ahalf = tid & 1;
    const __half* gA = A2 + (m0 + arow) * (size_t)K + ahalf * 32;
    const __half* gB = W2 + (n0 + arow) * (size_t)K + ahalf * 32;
    const uint32_t sts = (uint32_t)(arow * 128 + ahalf * 64);

    float acc[4][4][4];
#pragma unroll
    for (int i = 0; i < 4; i++)
#pragma unroll
        for (int j = 0; j < 4; j++)
#pragma unroll
            for (int r = 0; r < 4; r++) acc[i][j][r] = 0.f;

    auto issue = [&](int s) {
        const uint32_t ab = base + (uint32_t)(s % 3) * 32768u;
        const int k0 = s * 64;
#pragma unroll
        for (int c = 0; c < 4; c++) {
            const uint32_t sw = SW128(sts + (uint32_t)c * 16u);
            cp16(ab + sw, gA + k0 + c * 8);
            cp16(ab + 16384u + sw, gB + k0 + c * 8);
        }
    };

    issue(0); cp_commit();
    issue(1); cp_commit();

#pragma unroll 1
    for (int s = 0; s < ksteps; s++) {
        cp_wait1();              // stage s resident (stage s+1 may be pending)
        __syncthreads();         // all warps see stage s; all done with stage s-1
        if (s + 2 < ksteps) issue(s + 2);   // ring distance 2
        cp_commit();

        const uint32_t abase = base + (uint32_t)(s % 3) * 32768u;
        const uint32_t bbase = abase + 16384u;
#pragma unroll
        for (int kat = 0; kat < 4; kat++) {
            uint32_t af[4][4], bf[4][2];
#pragma unroll
            for (int i = 0; i < 4; i++) {
                uint32_t row = (uint32_t)(wm * 64 + i * 16 + (lane & 15));
                uint32_t byte = row * 128u + (uint32_t)kat * 32u + ((lane >> 4) << 4);
                ldsm_x4(af[i], abase + SW128(byte));
            }
#pragma unroll
            for (int jj = 0; jj < 2; jj++) {
                uint32_t row = (uint32_t)(wn * 32 + jj * 16 + ((lane >> 4) & 1) * 8 + (lane & 7));
                uint32_t byte = row * 128u + (uint32_t)kat * 32u + (((lane >> 3) & 1) << 4);
                uint32_t t[4];
                ldsm_x4(t, bbase + SW128(byte));
                bf[jj * 2][0] = t[0]; bf[jj * 2][1] = t[1];
                bf[jj * 2 + 1][0] = t[2]; bf[jj * 2 + 1][1] = t[3];
            }
#pragma unroll
            for (int i = 0; i < 4; i++)
#pragma unroll
                for (int j = 0; j < 4; j++)
                    mma16816(acc[i][j], af[i], bf[j]);
        }
    }

    // epilogue
    const int g = lane >> 2;
    const int tig = lane & 3;
#pragma unroll
    for (int i = 0; i < 4; i++) {
        const size_t r0 = m0 + wm * 64 + i * 16 + g;
#pragma unroll
        for (int j = 0; j < 4; j++) {
            const int col = (int)n0 + wn * 32 + j * 8 + tig * 2;
            const float2 bb = *(const float2*)(bias + col);
            const float v0 = acc[i][j][0] + bb.x, v1 = acc[i][j][1] + bb.y;
            const float v2 = acc[i][j][2] + bb.x, v3 = acc[i][j][3] + bb.y;
            if (Cf) {
                *(float2*)(Cf + r0 * N + col) = make_float2(v0, v1);
                *(float2*)(Cf + (r0 + 8) * N + col) = make_float2(v2, v3);
            } else if (Cl) {
                const float h0 = hround(v0), h1 = hround(v1);
                const float h2 = hround(v2), h3 = hround(v3);
                *(uint32_t*)(Ch + r0 * N + col) = pack2h(h0, h1);
                *(uint32_t*)(Cl + r0 * N + col) = pack2h(v0 - h0, v1 - h1);
                *(uint32_t*)(Ch + (r0 + 8) * N + col) = pack2h(h2, h3);
                *(uint32_t*)(Cl + (r0 + 8) * N + col) = pack2h(v2 - h2, v3 - h3);
            } else {
                *(uint32_t*)(Ch + r0 * N + col) = pack2h(v0, v1);
                *(uint32_t*)(Ch + (r0 + 8) * N + col) = pack2h(v2, v3);
            }
        }
    }
}

// ---------------------------------------------------------------------------
// Fused causal flash attention on tensor cores (plain fp16 operands,
// fp32 accumulate + fp32 softmax).  S = 0.125*(Qh·Kh);  O += Ph·Vh.
// grid (16 qtiles, 64 bh), 256 thr (8 warps), warp = 16 q-rows.
// K/V double-buffered cp.async; one barrier per kt-iteration.
// Epilogue emits EXACT ctx hi/lo split for GEMM2.
// smem: Qh 16KB + 2 x (Kh,Vh 16KB) = 48KB.
// ---------------------------------------------------------------------------
__global__ __launch_bounds__(256, 2) void attn_mma_kernel(
    const __half* __restrict__ qh_g, __half* __restrict__ a2ctx)
{
    extern __shared__ char smA[];
    const uint32_t dyn = smem_to_u32(smA);
    const uint32_t sb = (dyn + 1023u) & ~1023u;
    char* p = smA + (sb - dyn);
    const uint32_t QH = sb;

    const int tid = threadIdx.x;
    const int lane = tid & 31;
    const int w = tid >> 5;
    const int g = lane >> 2;
    const int tig = lane & 3;
    const int qt = blockIdx.x;
    const int bh = blockIdx.y;
    const int b = bh >> 4;
    const int hd = bh & 15;
    const int q0 = qt * 128;
    const int qw = q0 + w * 16;

    // K/V cp.async: tile = tid>>7 (0=Kh from +1024, 1=Vh from +2048), 2 thr/row
    const int kv_tile = tid >> 7;
    const int kv_r = (tid >> 1) & 63;
    const int kv_h = tid & 1;
    const __half* kv_src_base = qh_g + ((size_t)b * SEQ + kv_r) * 3072
        + (kv_tile ? 2048 : 1024) + hd * 64 + kv_h * 32;
    auto issue_kv = [&](int kt) {
        const uint32_t dst = sb + 16384u + (uint32_t)(kt & 1) * 16384u + (uint32_t)kv_tile * 8192u;
        const __half* src = kv_src_base + (size_t)kt * 64 * 3072;
#pragma unroll
        for (int c = 0; c < 4; c++)
            cp16(dst + SW128((uint32_t)(kv_r * 128 + kv_h * 64 + c * 16)), src + c * 8);
    };

    // Q hi tile: 128 rows x 128B (plain stores; covered by first barrier)
    {
        const int r = tid >> 1;
        const int hf = tid & 1;
        const __half* src = qh_g + ((size_t)b * SEQ + q0 + r) * 3072 + hd * 64 + hf * 32;
#pragma unroll
        for (int c = 0; c < 4; c++)
            *(uint4*)(p + SW128((uint32_t)(r * 128 + hf * 64 + c * 16))) = *(const uint4*)(src + c * 8);
    }

    issue_kv(0); cp_commit();

    float S[32], O[32];
#pragma unroll
    for (int i = 0; i < 32; i++) O[i] = 0.f;
    float m0 = -CUDART_INF_F, m1 = -CUDART_INF_F, l0 = 0.f, l1 = 0.f;

    const int ktmax = 2 * (qt + 1);
#pragma unroll 1
    for (int kt = 0; kt < ktmax; kt++) {
        const int k0 = kt * 64;
        cp_wait0();              // K/V stage kt resident
        __syncthreads();         // visible to all; all done with stage kt-1
        if (kt + 1 < ktmax) issue_kv(kt + 1);   // overlaps compute of kt
        cp_commit();

        const uint32_t kvb = sb + 16384u + (uint32_t)(kt & 1) * 16384u;
        const uint32_t KH = kvb, VH = kvb + 8192u;

        if (k0 <= qw + 15) {
#pragma unroll
            for (int i = 0; i < 32; i++) S[i] = 0.f;
            // ---- S = Qh·Kh
#pragma unroll
            for (int kat = 0; kat < 4; kat++) {
                const uint32_t swzA = SW128((uint32_t)((w * 16 + (lane & 15)) * 128
                                       + kat * 32 + ((lane >> 4) << 4)));
                uint32_t aqh[4];
                ldsm_x4(aqh, QH + swzA);
#pragma unroll
                for (int j2 = 0; j2 < 4; j2++) {
                    const uint32_t swzB = SW128((uint32_t)((j2 * 16 + ((lane >> 4) & 1) * 8
                                            + (lane & 7)) * 128 + kat * 32 + ((lane >> 3) & 1) * 16));
                    uint32_t bkh[4];
                    ldsm_x4(bkh, KH + swzB);
                    mma16816(&S[(2 * j2) * 4], aqh, bkh);
                    mma16816(&S[(2 * j2 + 1) * 4], aqh, bkh + 2);
                }
            }
            // ---- scale + causal mask + online softmax
            const int row0 = qw + g, row1 = row0 + 8;
            const bool msk = (k0 + 63 > qw);
            float tm0 = -CUDART_INF_F, tm1 = -CUDART_INF_F;
#pragma unroll
            for (int j = 0; j < 8; j++) {
                float* sj = &S[j * 4];
                sj[0] *= 0.125f; sj[1] *= 0.125f; sj[2] *= 0.125f; sj[3] *= 0.125f;
                if (msk) {
                    const int c0 = k0 + j * 8 + 2 * tig;
                    if (c0 > row0)     sj[0] = -CUDART_INF_F;
                    if (c0 + 1 > row0) sj[1] = -CUDART_INF_F;
                    if (c0 > row1)     sj[2] = -CUDART_INF_F;
                    if (c0 + 1 > row1) sj[3] = -CUDART_INF_F;
                }
                tm0 = fmaxf(tm0, fmaxf(sj[0], sj[1]));
                tm1 = fmaxf(tm1, fmaxf(sj[2], sj[3]));
            }
            tm0 = fmaxf(tm0, __shfl_xor_sync(0xffffffffu, tm0, 1));
            tm0 = fmaxf(tm0, __shfl_xor_sync(0xffffffffu, tm0, 2));
            tm1 = fmaxf(tm1, __shfl_xor_sync(0xffffffffu, tm1, 1));
            tm1 = fmaxf(tm1, __shfl_xor_sync(0xffffffffu, tm1, 2));
            const float mn0 = fmaxf(m0, tm0), mn1 = fmaxf(m1, tm1);
            const float corr0 = __expf(m0 - mn0), corr1 = __expf(m1 - mn1);
            m0 = mn0; m1 = mn1;

            float ls0 = 0.f, ls1 = 0.f;
            uint32_t PHf[16];
#pragma unroll
            for (int j = 0; j < 8; j++) {
                const float e0 = __expf(S[j * 4 + 0] - mn0);
                const float e1 = __expf(S[j * 4 + 1] - mn0);
                const float e2 = __expf(S[j * 4 + 2] - mn1);
                const float e3 = __expf(S[j * 4 + 3] - mn1);
                ls0 += e0 + e1; ls1 += e2 + e3;
                PHf[j * 2 + 0] = pack2h(e0, e1);
                PHf[j * 2 + 1] = pack2h(e2, e3);
            }
            ls0 += __shfl_xor_sync(0xffffffffu, ls0, 1);
            ls0 += __shfl_xor_sync(0xffffffffu, ls0, 2);
            ls1 += __shfl_xor_sync(0xffffffffu, ls1, 1);
            ls1 += __shfl_xor_sync(0xffffffffu, ls1, 2);
            l0 = l0 * corr0 + ls0;
            l1 = l1 * corr1 + ls1;
#pragma unroll
            for (int j = 0; j < 8; j++) {
                O[j * 4 + 0] *= corr0; O[j * 4 + 1] *= corr0;
                O[j * 4 + 2] *= corr1; O[j * 4 + 3] *= corr1;
            }
            // ---- O += Ph·Vh   (V^T via ldmatrix.trans)
#pragma unroll
            for (int kat = 0; kat < 4; kat++) {
#pragma unroll
                for (int jd2 = 0; jd2 < 4; jd2++) {
                    const uint32_t swzV = SW128((uint32_t)((kat * 16 + ((lane >> 3) & 1) * 8
                                            + (lane & 7)) * 128 + jd2 * 32 + ((lane >> 4) & 1) * 16));
                    uint32_t bvh[4];
                    ldsm_x4_t(bvh, VH + swzV);
                    mma16816(&O[(2 * jd2) * 4], &PHf[4 * kat], bvh);
                    mma16816(&O[(2 * jd2 + 1) * 4], &PHf[4 * kat], bvh + 2);
                }
            }
        }
    }

    // epilogue: normalized O -> EXACT ctx hi/lo split rows (width 2048)
    const float inv0 = 1.f / l0, inv1 = 1.f / l1;
    __half* rp0 = a2ctx + ((size_t)b * SEQ + qw + g) * K2 + hd * 64;
    __half* rp1 = rp0 + (size_t)8 * K2;
#pragma unroll
    for (int j = 0; j < 8; j++) {
        const int c = j * 8 + 2 * tig;
        {
            const float v0 = O[j * 4 + 0] * inv0, v1 = O[j * 4 + 1] * inv0;
            const float h0 = hround(v0), h1 = hround(v1);
            *(uint32_t*)(rp0 + c) = pack2h(h0, h1);
            *(uint32_t*)(rp0 + 1024 + c) = pack2h(v0 - h0, v1 - h1);
        }
        {
            const float v2 = O[j * 4 + 2] * inv1, v3 = O[j * 4 + 3] * inv1;
            const float h2 = hround(v2), h3 = hround(v3);
            *(uint32_t*)(rp1 + c) = pack2h(h2, h3);
            *(uint32_t*)(rp1 + 1024 + c) = pack2h(v2 - h2, v3 - h3);
        }
    }
}

// ---------------------------------------------------------------------------
extern "C" void kernel_launch(void* const* d_in, const int* in_sizes, int n_in,
                              void* d_out, int out_size)
{
    (void)in_sizes; (void)n_in; (void)out_size;
    const float* x     = (const float*)d_in[0];
    const float* W_qkv = (const float*)d_in[2];
    const float* b_qkv = (const float*)d_in[3];
    const float* W_out = (const float*)d_in[4];
    const float* b_out = (const float*)d_in[5];
    float* out = (float*)d_out;

    __half *xh, *wqkv, *a2ctx, *w2out, *qh;
    cudaGetSymbolAddress((void**)&xh, g_xh);
    cudaGetSymbolAddress((void**)&wqkv, g_wqkv);
    cudaGetSymbolAddress((void**)&a2ctx, g_a2ctx);
    cudaGetSymbolAddress((void**)&w2out, g_w2out);
    cudaGetSymbolAddress((void**)&qh, g_qh);

    const int gsmem = 97 * 1024;   // 3x32KB ring + align
    const int asmem = 50 * 1024;   // 16KB Q + 2x16KB KV + align
    cudaFuncSetAttribute(gemm_mma_kernel, cudaFuncAttributeMaxDynamicSharedMemorySize, gsmem);
    cudaFuncSetAttribute(gemm_mma_kernel, cudaFuncAttributePreferredSharedMemoryCarveout, 100);
    cudaFuncSetAttribute(attn_mma_kernel, cudaFuncAttributeMaxDynamicSharedMemorySize, asmem);
    cudaFuncSetAttribute(attn_mma_kernel, cudaFuncAttributePreferredSharedMemoryCarveout, 100);

    // 0) fp32 -> fp16 conversions
    conv_kernel<<<(BT * HID / 4 + 255) / 256, 256>>>(x, xh, HID, (size_t)BT * HID / 4, 0);
    conv_kernel<<<(3 * HID * HID / 4 + 255) / 256, 256>>>(W_qkv, wqkv, HID, (size_t)3 * HID * HID / 4, 0);
    conv_kernel<<<(HID * HID / 4 + 255) / 256, 256>>>(W_out, w2out, HID, (size_t)HID * HID / 4, 1);

    // 1) QKV projection (HMMA fp16, K=1024) -> qkv hi only
    gemm_mma_kernel<<<dim3(3 * HID / 128, BT / 128), 256, gsmem>>>(
        xh, wqkv, b_qkv, nullptr, qh, nullptr, 3 * HID, HID);

    // 2) fused causal attention (HMMA fp16) -> EXACT split-fp16 ctx
    attn_mma_kernel<<<dim3(SEQ / 128, 4 * NHEADS), 256, asmem>>>(qh, a2ctx);

    // 3) output projection (HMMA fp16, K=2048): exact ctx hi/lo -> fp32 out
    gemm_mma_kernel<<<dim3(HID / 128, BT / 128), 256, gsmem>>>(
        a2ctx, w2out, b_out, out, nullptr, nullptr, HID, K2);
}

// round 15
// speedup vs baseline: 1.8166x; 1.1440x over previous
#include <cuda_runtime.h>
#include <cuda_fp16.h>
#include <math_constants.h>
#include <cstdint>

#define HID 1024
#define NHEADS 16
#define HDIM 64
#define SEQ 2048
#define BT 8192

// ---------------------------------------------------------------------------
// Scratch (__device__ globals: runtime allocation is forbidden)
// ---------------------------------------------------------------------------
__device__ __half g_xh[(size_t)BT * HID];          // x hi (fp16)
__device__ __half g_wqkv[(size_t)3 * HID * HID];   // W_qkv hi (fp16)
__device__ __half g_ctx[(size_t)BT * HID];         // ctx (fp16)
__device__ __half g_wout[(size_t)HID * HID];       // W_out hi (fp16)
__device__ __half g_qh[(size_t)BT * 3 * HID];      // qkv hi (fp16)

// ---------------------------------------------------------------------------
// helpers
// ---------------------------------------------------------------------------
__device__ __forceinline__ uint32_t smem_to_u32(const void* p) {
    uint32_t a;
    asm("{ .reg .u64 t; cvta.to.shared.u64 t, %1; cvt.u32.u64 %0, t; }"
        : "=r"(a) : "l"(p));
    return a;
}
#define SW128(b) ((b) ^ (((b) >> 3) & 0x70u))

__device__ __forceinline__ void ldsm_x4(uint32_t* r, uint32_t addr) {
    asm volatile("ldmatrix.sync.aligned.m8n8.x4.shared.b16 {%0,%1,%2,%3}, [%4];"
        : "=r"(r[0]), "=r"(r[1]), "=r"(r[2]), "=r"(r[3]) : "r"(addr));
}
__device__ __forceinline__ void ldsm_x4_t(uint32_t* r, uint32_t addr) {
    asm volatile("ldmatrix.sync.aligned.m8n8.x4.trans.shared.b16 {%0,%1,%2,%3}, [%4];"
        : "=r"(r[0]), "=r"(r[1]), "=r"(r[2]), "=r"(r[3]) : "r"(addr));
}
__device__ __forceinline__ void mma16816(float* d, const uint32_t* a, const uint32_t* b) {
    asm volatile("mma.sync.aligned.m16n8k16.row.col.f32.f16.f16.f32 "
        "{%0,%1,%2,%3}, {%4,%5,%6,%7}, {%8,%9}, {%0,%1,%2,%3};"
        : "+f"(d[0]), "+f"(d[1]), "+f"(d[2]), "+f"(d[3])
        : "r"(a[0]), "r"(a[1]), "r"(a[2]), "r"(a[3]), "r"(b[0]), "r"(b[1]));
}
__device__ __forceinline__ void cp16(uint32_t dst, const void* src) {
    asm volatile("cp.async.cg.shared.global [%0], [%1], 16;" :: "r"(dst), "l"(src));
}
__device__ __forceinline__ void cp_commit() { asm volatile("cp.async.commit_group;" ::: "memory"); }
__device__ __forceinline__ void cp_wait1()  { asm volatile("cp.async.wait_group 1;" ::: "memory"); }
__device__ __forceinline__ void cp_wait0()  { asm volatile("cp.async.wait_group 0;" ::: "memory"); }

__device__ __forceinline__ uint32_t pack2h(float a, float b) {
    __half2 t = __floats2half2_rn(a, b);
    return *reinterpret_cast<uint32_t*>(&t);
}
__device__ __forceinline__ float hround(float v) {
    return __half2float(__float2half_rn(v));
}

// ---------------------------------------------------------------------------
// Convert: src fp32 [rows, K] -> dst fp16 [rows, K]
// ---------------------------------------------------------------------------
__global__ __launch_bounds__(256) void conv_kernel(
    const float* __restrict__ src, __half* __restrict__ dst,
    int K, size_t total4)
{
    size_t idx = (size_t)blockIdx.x * blockDim.x + threadIdx.x;
    if (idx >= total4) return;
    int kq = K >> 2;
    size_t r = idx / kq;
    int c = (int)(idx % kq) << 2;
    float4 v = *(const float4*)(src + r * K + c);
    uint2 hi = make_uint2(pack2h(hround(v.x), hround(v.y)),
                          pack2h(hround(v.z), hround(v.w)));
    *(uint2*)(dst + r * K + c) = hi;
}

// ---------------------------------------------------------------------------
// mma.sync fp16 GEMM: C[M,N] = A[M,K] @ W[N,K]^T + bias   (K runtime, %64==0)
// CTA 128x128, BK=64, 256 thr (8 warps 2x4), warp tile 64x32.
// 3-stage cp.async ring, one barrier per k-step.
// Epilogue: fp32 (Cf) or fp16 (Ch).
// ---------------------------------------------------------------------------
__global__ __launch_bounds__(256, 2) void gemm_mma_kernel(
    const __half* __restrict__ A2, const __half* __restrict__ W2,
    const float* __restrict__ bias, float* __restrict__ Cf,
    __half* __restrict__ Ch, int N, int K)
{
    extern __shared__ char dsm[];
    const uint32_t dyn = smem_to_u32(dsm);
    const uint32_t base = (dyn + 1023u) & ~1023u;

    const int tid = threadIdx.x;
    const int lane = tid & 31;
    const int wid = tid >> 5;
    const int wm = wid >> 2;
    const int wn = wid & 3;
    const size_t m0 = (size_t)blockIdx.y * 128;
    const size_t n0 = (size_t)blockIdx.x * 128;
    const int ksteps = K >> 6;

    const int arow = tid >> 1;
    const int ahalf = tid & 1;
    const __half* gA = A2 + (m0 + arow) * (size_t)K + ahalf * 32;
    const __half* gB = W2 + (n0 + arow) * (size_t)K + ahalf * 32;
    const uint32_t sts = (uint32_t)(arow * 128 + ahalf * 64);

    float acc[4][4][4];
#pragma unroll
    for (int i = 0; i < 4; i++)
#pragma unroll
        for (int j = 0; j < 4; j++)
#pragma unroll
            for (int r = 0; r < 4; r++) acc[i][j][r] = 0.f;

    auto issue = [&](int s) {
        const uint32_t ab = base + (uint32_t)(s % 3) * 32768u;
        const int k0 = s * 64;
#pragma unroll
        for (int c = 0; c < 4; c++) {
            const uint32_t sw = SW128(sts + (uint32_t)c * 16u);
            cp16(ab + sw, gA + k0 + c * 8);
            cp16(ab + 16384u + sw, gB + k0 + c * 8);
        }
    };

    issue(0); cp_commit();
    issue(1); cp_commit();

#pragma unroll 1
    for (int s = 0; s < ksteps; s++) {
        cp_wait1();              // stage s resident (stage s+1 may be pending)
        __syncthreads();         // all warps see stage s; all done with stage s-1
        if (s + 2 < ksteps) issue(s + 2);   // ring distance 2
        cp_commit();

        const uint32_t abase = base + (uint32_t)(s % 3) * 32768u;
        const uint32_t bbase = abase + 16384u;
#pragma unroll
        for (int kat = 0; kat < 4; kat++) {
            uint32_t af[4][4], bf[4][2];
#pragma unroll
            for (int i = 0; i < 4; i++) {
                uint32_t row = (uint32_t)(wm * 64 + i * 16 + (lane & 15));
                uint32_t byte = row * 128u + (uint32_t)kat * 32u + ((lane >> 4) << 4);
                ldsm_x4(af[i], abase + SW128(byte));
            }
#pragma unroll
            for (int jj = 0; jj < 2; jj++) {
                uint32_t row = (uint32_t)(wn * 32 + jj * 16 + ((lane >> 4) & 1) * 8 + (lane & 7));
                uint32_t byte = row * 128u + (uint32_t)kat * 32u + (((lane >> 3) & 1) << 4);
                uint32_t t[4];
                ldsm_x4(t, bbase + SW128(byte));
                bf[jj * 2][0] = t[0]; bf[jj * 2][1] = t[1];
                bf[jj * 2 + 1][0] = t[2]; bf[jj * 2 + 1][1] = t[3];
            }
#pragma unroll
            for (int i = 0; i < 4; i++)
#pragma unroll
                for (int j = 0; j < 4; j++)
                    mma16816(acc[i][j], af[i], bf[j]);
        }
    }

    // epilogue
    const int g = lane >> 2;
    const int tig = lane & 3;
#pragma unroll
    for (int i = 0; i < 4; i++) {
        const size_t r0 = m0 + wm * 64 + i * 16 + g;
#pragma unroll
        for (int j = 0; j < 4; j++) {
            const int col = (int)n0 + wn * 32 + j * 8 + tig * 2;
            const float2 bb = *(const float2*)(bias + col);
            const float v0 = acc[i][j][0] + bb.x, v1 = acc[i][j][1] + bb.y;
            const float v2 = acc[i][j][2] + bb.x, v3 = acc[i][j][3] + bb.y;
            if (Cf) {
                *(float2*)(Cf + r0 * N + col) = make_float2(v0, v1);
                *(float2*)(Cf + (r0 + 8) * N + col) = make_float2(v2, v3);
            } else {
                *(uint32_t*)(Ch + r0 * N + col) = pack2h(v0, v1);
                *(uint32_t*)(Ch + (r0 + 8) * N + col) = pack2h(v2, v3);
            }
        }
    }
}

// ---------------------------------------------------------------------------
// Fused causal flash attention on tensor cores (fp16 operands, fp32 softmax).
// S = 0.125*(Qh·Kh);  O += Ph·Vh.
// grid (16 qtiles, 64 bh), 256 thr (8 warps), warp = 16 q-rows.
// K/V double-buffered cp.async; one barrier per kt-iteration.
// Epilogue emits plain fp16 ctx [BT, HID].
// smem: Qh 16KB + 2 x (Kh,Vh 16KB) = 48KB.
// ---------------------------------------------------------------------------
__global__ __launch_bounds__(256, 2) void attn_mma_kernel(
    const __half* __restrict__ qh_g, __half* __restrict__ ctx)
{
    extern __shared__ char smA[];
    const uint32_t dyn = smem_to_u32(smA);
    const uint32_t sb = (dyn + 1023u) & ~1023u;
    char* p = smA + (sb - dyn);
    const uint32_t QH = sb;

    const int tid = threadIdx.x;
    const int lane = tid & 31;
    const int w = tid >> 5;
    const int g = lane >> 2;
    const int tig = lane & 3;
    const int qt = blockIdx.x;
    const int bh = blockIdx.y;
    const int b = bh >> 4;
    const int hd = bh & 15;
    const int q0 = qt * 128;
    const int qw = q0 + w * 16;

    // K/V cp.async: tile = tid>>7 (0=Kh from +1024, 1=Vh from +2048), 2 thr/row
    const int kv_tile = tid >> 7;
    const int kv_r = (tid >> 1) & 63;
    const int kv_h = tid & 1;
    const __half* kv_src_base = qh_g + ((size_t)b * SEQ + kv_r) * 3072
        + (kv_tile ? 2048 : 1024) + hd * 64 + kv_h * 32;
    auto issue_kv = [&](int kt) {
        const uint32_t dst = sb + 16384u + (uint32_t)(kt & 1) * 16384u + (uint32_t)kv_tile * 8192u;
        const __half* src = kv_src_base + (size_t)kt * 64 * 3072;
#pragma unroll
        for (int c = 0; c < 4; c++)
            cp16(dst + SW128((uint32_t)(kv_r * 128 + kv_h * 64 + c * 16)), src + c * 8);
    };

    // Q hi tile: 128 rows x 128B (plain stores; covered by first barrier)
    {
        const int r = tid >> 1;
        const int hf = tid & 1;
        const __half* src = qh_g + ((size_t)b * SEQ + q0 + r) * 3072 + hd * 64 + hf * 32;
#pragma unroll
        for (int c = 0; c < 4; c++)
            *(uint4*)(p + SW128((uint32_t)(r * 128 + hf * 64 + c * 16))) = *(const uint4*)(src + c * 8);
    }

    issue_kv(0); cp_commit();

    float S[32], O[32];
#pragma unroll
    for (int i = 0; i < 32; i++) O[i] = 0.f;
    float m0 = -CUDART_INF_F, m1 = -CUDART_INF_F, l0 = 0.f, l1 = 0.f;

    const int ktmax = 2 * (qt + 1);
#pragma unroll 1
    for (int kt = 0; kt < ktmax; kt++) {
        const int k0 = kt * 64;
        cp_wait0();              // K/V stage kt resident
        __syncthreads();         // visible to all; all done with stage kt-1
        if (kt + 1 < ktmax) issue_kv(kt + 1);   // overlaps compute of kt
        cp_commit();

        const uint32_t kvb = sb + 16384u + (uint32_t)(kt & 1) * 16384u;
        const uint32_t KH = kvb, VH = kvb + 8192u;

        if (k0 <= qw + 15) {
#pragma unroll
            for (int i = 0; i < 32; i++) S[i] = 0.f;
            // ---- S = Qh·Kh
#pragma unroll
            for (int kat = 0; kat < 4; kat++) {
                const uint32_t swzA = SW128((uint32_t)((w * 16 + (lane & 15)) * 128
                                       + kat * 32 + ((lane >> 4) << 4)));
                uint32_t aqh[4];
                ldsm_x4(aqh, QH + swzA);
#pragma unroll
                for (int j2 = 0; j2 < 4; j2++) {
                    const uint32_t swzB = SW128((uint32_t)((j2 * 16 + ((lane >> 4) & 1) * 8
                                            + (lane & 7)) * 128 + kat * 32 + ((lane >> 3) & 1) * 16));
                    uint32_t bkh[4];
                    ldsm_x4(bkh, KH + swzB);
                    mma16816(&S[(2 * j2) * 4], aqh, bkh);
                    mma16816(&S[(2 * j2 + 1) * 4], aqh, bkh + 2);
                }
            }
            // ---- scale + causal mask + online softmax
            const int row0 = qw + g, row1 = row0 + 8;
            const bool msk = (k0 + 63 > qw);
            float tm0 = -CUDART_INF_F, tm1 = -CUDART_INF_F;
#pragma unroll
            for (int j = 0; j < 8; j++) {
                float* sj = &S[j * 4];
                sj[0] *= 0.125f; sj[1] *= 0.125f; sj[2] *= 0.125f; sj[3] *= 0.125f;
                if (msk) {
                    const int c0 = k0 + j * 8 + 2 * tig;
                    if (c0 > row0)     sj[0] = -CUDART_INF_F;
                    if (c0 + 1 > row0) sj[1] = -CUDART_INF_F;
                    if (c0 > row1)     sj[2] = -CUDART_INF_F;
                    if (c0 + 1 > row1) sj[3] = -CUDART_INF_F;
                }
                tm0 = fmaxf(tm0, fmaxf(sj[0], sj[1]));
                tm1 = fmaxf(tm1, fmaxf(sj[2], sj[3]));
            }
            tm0 = fmaxf(tm0, __shfl_xor_sync(0xffffffffu, tm0, 1));
            tm0 = fmaxf(tm0, __shfl_xor_sync(0xffffffffu, tm0, 2));
            tm1 = fmaxf(tm1, __shfl_xor_sync(0xffffffffu, tm1, 1));
            tm1 = fmaxf(tm1, __shfl_xor_sync(0xffffffffu, tm1, 2));
            const float mn0 = fmaxf(m0, tm0), mn1 = fmaxf(m1, tm1);
            const float corr0 = __expf(m0 - mn0), corr1 = __expf(m1 - mn1);
            m0 = mn0; m1 = mn1;

            float ls0 = 0.f, ls1 = 0.f;
            uint32_t PHf[16];
#pragma unroll
            for (int j = 0; j < 8; j++) {
                const float e0 = __expf(S[j * 4 + 0] - mn0);
                const float e1 = __expf(S[j * 4 + 1] - mn0);
                const float e2 = __expf(S[j * 4 + 2] - mn1);
                const float e3 = __expf(S[j * 4 + 3] - mn1);
                ls0 += e0 + e1; ls1 += e2 + e3;
                PHf[j * 2 + 0] = pack2h(e0, e1);
                PHf[j * 2 + 1] = pack2h(e2, e3);
            }
            ls0 += __shfl_xor_sync(0xffffffffu, ls0, 1);
            ls0 += __shfl_xor_sync(0xffffffffu, ls0, 2);
            ls1 += __shfl_xor_sync(0xffffffffu, ls1, 1);
            ls1 += __shfl_xor_sync(0xffffffffu, ls1, 2);
            l0 = l0 * corr0 + ls0;
            l1 = l1 * corr1 + ls1;
#pragma unroll
            for (int j = 0; j < 8; j++) {
                O[j * 4 + 0] *= corr0; O[j * 4 + 1] *= corr0;
                O[j * 4 + 2] *= corr1; O[j * 4 + 3] *= corr1;
            }
            // ---- O += Ph·Vh   (V^T via ldmatrix.trans)
#pragma unroll
            for (int kat = 0; kat < 4; kat++) {
#pragma unroll
                for (int jd2 = 0; jd2 < 4; jd2++) {
                    const uint32_t swzV = SW128((uint32_t)((kat * 16 + ((lane >> 3) & 1) * 8
                                            + (lane & 7)) * 128 + jd2 * 32 + ((lane >> 4) & 1) * 16));
                    uint32_t bvh[4];
                    ldsm_x4_t(bvh, VH + swzV);
                    mma16816(&O[(2 * jd2) * 4], &PHf[4 * kat], bvh);
                    mma16816(&O[(2 * jd2 + 1) * 4], &PHf[4 * kat], bvh + 2);
                }
            }
        }
    }

    // epilogue: normalized O -> plain fp16 ctx rows (width 1024)
    const float inv0 = 1.f / l0, inv1 = 1.f / l1;
    __half* rp0 = ctx + ((size_t)b * SEQ + qw + g) * HID + hd * 64;
    __half* rp1 = rp0 + (size_t)8 * HID;
#pragma unroll
    for (int j = 0; j < 8; j++) {
        const int c = j * 8 + 2 * tig;
        *(uint32_t*)(rp0 + c) = pack2h(O[j * 4 + 0] * inv0, O[j * 4 + 1] * inv0);
        *(uint32_t*)(rp1 + c) = pack2h(O[j * 4 + 2] * inv1, O[j * 4 + 3] * inv1);
    }
}

// ---------------------------------------------------------------------------
extern "C" void kernel_launch(void* const* d_in, const int* in_sizes, int n_in,
                              void* d_out, int out_size)
{
    (void)in_sizes; (void)n_in; (void)out_size;
    const float* x     = (const float*)d_in[0];
    const float* W_qkv = (const float*)d_in[2];
    const float* b_qkv = (const float*)d_in[3];
    const float* W_out = (const float*)d_in[4];
    const float* b_out = (const float*)d_in[5];
    float* out = (float*)d_out;

    __half *xh, *wqkv, *ctx, *wout, *qh;
    cudaGetSymbolAddress((void**)&xh, g_xh);
    cudaGetSymbolAddress((void**)&wqkv, g_wqkv);
    cudaGetSymbolAddress((void**)&ctx, g_ctx);
    cudaGetSymbolAddress((void**)&wout, g_wout);
    cudaGetSymbolAddress((void**)&qh, g_qh);

    const int gsmem = 97 * 1024;   // 3x32KB ring + align
    const int asmem = 50 * 1024;   // 16KB Q + 2x16KB KV + align
    cudaFuncSetAttribute(gemm_mma_kernel, cudaFuncAttributeMaxDynamicSharedMemorySize, gsmem);
    cudaFuncSetAttribute(gemm_mma_kernel, cudaFuncAttributePreferredSharedMemoryCarveout, 100);
    cudaFuncSetAttribute(attn_mma_kernel, cudaFuncAttributeMaxDynamicSharedMemorySize, asmem);
    cudaFuncSetAttribute(attn_mma_kernel, cudaFuncAttributePreferredSharedMemoryCarveout, 100);

    // 0) fp32 -> fp16 conversions
    conv_kernel<<<(BT * HID / 4 + 255) / 256, 256>>>(x, xh, HID, (size_t)BT * HID / 4);
    conv_kernel<<<(3 * HID * HID / 4 + 255) / 256, 256>>>(W_qkv, wqkv, HID, (size_t)3 * HID * HID / 4);
    conv_kernel<<<(HID * HID / 4 + 255) / 256, 256>>>(W_out, wout, HID, (size_t)HID * HID / 4);

    // 1) QKV projection (HMMA fp16, K=1024) -> qkv hi
    gemm_mma_kernel<<<dim3(3 * HID / 128, BT / 128), 256, gsmem>>>(
        xh, wqkv, b_qkv, nullptr, qh, 3 * HID, HID);

    // 2) fused causal attention (HMMA fp16) -> fp16 ctx
    attn_mma_kernel<<<dim3(SEQ / 128, 4 * NHEADS), 256, asmem>>>(qh, ctx);

    // 3) output projection (HMMA fp16, K=1024) -> fp32 out
    gemm_mma_kernel<<<dim3(HID / 128, BT / 128), 256, gsmem>>>(
        ctx, wout, b_out, out, nullptr, HID, HID);
}

// round 16
// speedup vs baseline: 1.8327x; 1.0088x over previous
#include <cuda_runtime.h>
#include <cuda_fp16.h>
#include <math_constants.h>
#include <cstdint>

#define HID 1024
#define NHEADS 16
#define HDIM 64
#define SEQ 2048
#define BT 8192

// ---------------------------------------------------------------------------
// Scratch (__device__ globals: runtime allocation is forbidden)
// ---------------------------------------------------------------------------
__device__ __half g_xh[(size_t)BT * HID];          // x hi (fp16)
__device__ __half g_wqkv[(size_t)3 * HID * HID];   // W_qkv hi (fp16)
__device__ __half g_ctx[(size_t)BT * HID];         // ctx (fp16)
__device__ __half g_wout[(size_t)HID * HID];       // W_out hi (fp16)
__device__ __half g_qh[(size_t)BT * 3 * HID];      // qkv hi (fp16)

// ---------------------------------------------------------------------------
// helpers
// ---------------------------------------------------------------------------
__device__ __forceinline__ uint32_t smem_to_u32(const void* p) {
    uint32_t a;
    asm("{ .reg .u64 t; cvta.to.shared.u64 t, %1; cvt.u32.u64 %0, t; }"
        : "=r"(a) : "l"(p));
    return a;
}
#define SW128(b) ((b) ^ (((b) >> 3) & 0x70u))

__device__ __forceinline__ void ldsm_x4(uint32_t* r, uint32_t addr) {
    asm volatile("ldmatrix.sync.aligned.m8n8.x4.shared.b16 {%0,%1,%2,%3}, [%4];"
        : "=r"(r[0]), "=r"(r[1]), "=r"(r[2]), "=r"(r[3]) : "r"(addr));
}
__device__ __forceinline__ void ldsm_x4_t(uint32_t* r, uint32_t addr) {
    asm volatile("ldmatrix.sync.aligned.m8n8.x4.trans.shared.b16 {%0,%1,%2,%3}, [%4];"
        : "=r"(r[0]), "=r"(r[1]), "=r"(r[2]), "=r"(r[3]) : "r"(addr));
}
__device__ __forceinline__ void mma16816(float* d, const uint32_t* a, const uint32_t* b) {
    asm volatile("mma.sync.aligned.m16n8k16.row.col.f32.f16.f16.f32 "
        "{%0,%1,%2,%3}, {%4,%5,%6,%7}, {%8,%9}, {%0,%1,%2,%3};"
        : "+f"(d[0]), "+f"(d[1]), "+f"(d[2]), "+f"(d[3])
        : "r"(a[0]), "r"(a[1]), "r"(a[2]), "r"(a[3]), "r"(b[0]), "r"(b[1]));
}
__device__ __forceinline__ void cp16(uint32_t dst, const void* src) {
    asm volatile("cp.async.cg.shared.global [%0], [%1], 16;" :: "r"(dst), "l"(src));
}
__device__ __forceinline__ void cp_commit() { asm volatile("cp.async.commit_group;" ::: "memory"); }
__device__ __forceinline__ void cp_wait1()  { asm volatile("cp.async.wait_group 1;" ::: "memory"); }
__device__ __forceinline__ void cp_wait0()  { asm volatile("cp.async.wait_group 0;" ::: "memory"); }

__device__ __forceinline__ uint32_t pack2h(float a, float b) {
    __half2 t = __floats2half2_rn(a, b);
    return *reinterpret_cast<uint32_t*>(&t);
}

// ---------------------------------------------------------------------------
// Merged flat convert: three fp32 arrays -> fp16, one launch.
// ---------------------------------------------------------------------------
__global__ __launch_bounds__(256) void conv3_kernel(
    const float* __restrict__ s0, __half* __restrict__ d0, size_t n0,
    const float* __restrict__ s1, __half* __restrict__ d1, size_t n1,
    const float* __restrict__ s2, __half* __restrict__ d2, size_t n2)
{
    size_t i = ((size_t)blockIdx.x * blockDim.x + threadIdx.x) * 4;
    const float* s; __half* d; size_t off;
    if (i < n0)                { s = s0; d = d0; off = i; }
    else if (i < n0 + n1)      { s = s1; d = d1; off = i - n0; }
    else if (i < n0 + n1 + n2) { s = s2; d = d2; off = i - n0 - n1; }
    else return;
    float4 v = *(const float4*)(s + off);
    *(uint2*)(d + off) = make_uint2(pack2h(v.x, v.y), pack2h(v.z, v.w));
}

// ---------------------------------------------------------------------------
// mma.sync fp16 GEMM: C[M,N] = A[M,K] @ W[N,K]^T + bias   (K runtime, %64==0)
// CTA 128x128, BK=64, 256 thr (8 warps 2x4), warp tile 64x32.
// 3-stage cp.async ring, one barrier per k-step.
// Epilogue: fp32 (Cf) or fp16 (Ch).
// ---------------------------------------------------------------------------
__global__ __launch_bounds__(256, 2) void gemm_mma_kernel(
    const __half* __restrict__ A2, const __half* __restrict__ W2,
    const float* __restrict__ bias, float* __restrict__ Cf,
    __half* __restrict__ Ch, int N, int K)
{
    extern __shared__ char dsm[];
    const uint32_t dyn = smem_to_u32(dsm);
    const uint32_t base = (dyn + 1023u) & ~1023u;

    const int tid = threadIdx.x;
    const int lane = tid & 31;
    const int wid = tid >> 5;
    const int wm = wid >> 2;
    const int wn = wid & 3;
    const size_t m0 = (size_t)blockIdx.y * 128;
    const size_t n0 = (size_t)blockIdx.x * 128;
    const int ksteps = K >> 6;

    const int arow = tid >> 1;
    const int ahalf = tid & 1;
    const __half* gA = A2 + (m0 + arow) * (size_t)K + ahalf * 32;
    const __half* gB = W2 + (n0 + arow) * (size_t)K + ahalf * 32;
    const uint32_t sts = (uint32_t)(arow * 128 + ahalf * 64);

    float acc[4][4][4];
#pragma unroll
    for (int i = 0; i < 4; i++)
#pragma unroll
        for (int j = 0; j < 4; j++)
#pragma unroll
            for (int r = 0; r < 4; r++) acc[i][j][r] = 0.f;

    auto issue = [&](int s) {
        const uint32_t ab = base + (uint32_t)(s % 3) * 32768u;
        const int k0 = s * 64;
#pragma unroll
        for (int c = 0; c < 4; c++) {
            const uint32_t sw = SW128(sts + (uint32_t)c * 16u);
            cp16(ab + sw, gA + k0 + c * 8);
            cp16(ab + 16384u + sw, gB + k0 + c * 8);
        }
    };

    issue(0); cp_commit();
    issue(1); cp_commit();

#pragma unroll 1
    for (int s = 0; s < ksteps; s++) {
        cp_wait1();              // stage s resident (stage s+1 may be pending)
        __syncthreads();         // all warps see stage s; all done with stage s-1
        if (s + 2 < ksteps) issue(s + 2);   // ring distance 2
        cp_commit();

        const uint32_t abase = base + (uint32_t)(s % 3) * 32768u;
        const uint32_t bbase = abase + 16384u;
#pragma unroll
        for (int kat = 0; kat < 4; kat++) {
            uint32_t af[4][4], bf[4][2];
#pragma unroll
            for (int i = 0; i < 4; i++) {
                uint32_t row = (uint32_t)(wm * 64 + i * 16 + (lane & 15));
                uint32_t byte = row * 128u + (uint32_t)kat * 32u + ((lane >> 4) << 4);
                ldsm_x4(af[i], abase + SW128(byte));
            }
#pragma unroll
            for (int jj = 0; jj < 2; jj++) {
                uint32_t row = (uint32_t)(wn * 32 + jj * 16 + ((lane >> 4) & 1) * 8 + (lane & 7));
                uint32_t byte = row * 128u + (uint32_t)kat * 32u + (((lane >> 3) & 1) << 4);
                uint32_t t[4];
                ldsm_x4(t, bbase + SW128(byte));
                bf[jj * 2][0] = t[0]; bf[jj * 2][1] = t[1];
                bf[jj * 2 + 1][0] = t[2]; bf[jj * 2 + 1][1] = t[3];
            }
#pragma unroll
            for (int i = 0; i < 4; i++)
#pragma unroll
                for (int j = 0; j < 4; j++)
                    mma16816(acc[i][j], af[i], bf[j]);
        }
    }

    // epilogue
    const int g = lane >> 2;
    const int tig = lane & 3;
#pragma unroll
    for (int i = 0; i < 4; i++) {
        const size_t r0 = m0 + wm * 64 + i * 16 + g;
#pragma unroll
        for (int j = 0; j < 4; j++) {
            const int col = (int)n0 + wn * 32 + j * 8 + tig * 2;
            const float2 bb = *(const float2*)(bias + col);
            const float v0 = acc[i][j][0] + bb.x, v1 = acc[i][j][1] + bb.y;
            const float v2 = acc[i][j][2] + bb.x, v3 = acc[i][j][3] + bb.y;
            if (Cf) {
                *(float2*)(Cf + r0 * N + col) = make_float2(v0, v1);
                *(float2*)(Cf + (r0 + 8) * N + col) = make_float2(v2, v3);
            } else {
                *(uint32_t*)(Ch + r0 * N + col) = pack2h(v0, v1);
                *(uint32_t*)(Ch + (r0 + 8) * N + col) = pack2h(v2, v3);
            }
        }
    }
}

// ---------------------------------------------------------------------------
// Fused causal flash attention on tensor cores (fp16 operands, fp32 softmax).
// S = 0.125*(Qh·Kh);  O += Ph·Vh.
// grid (16 qtiles, 64 bh), 256 thr (8 warps), warp = 16 q-rows.
// TK=128: each cp.async stage carries 128-key K+V; two 64-key halves are
// processed per barrier (identical arithmetic order to TK=64 version).
// Heavy q-tiles launch first (qt reversed) for better wave packing.
// smem: Qh 16KB + 2 x 32KB KV stages = 80KB.
// ---------------------------------------------------------------------------
__global__ __launch_bounds__(256, 2) void attn_mma_kernel(
    const __half* __restrict__ qh_g, __half* __restrict__ ctx)
{
    extern __shared__ char smA[];
    const uint32_t dyn = smem_to_u32(smA);
    const uint32_t sb = (dyn + 1023u) & ~1023u;
    char* p = smA + (sb - dyn);
    const uint32_t QH = sb;

    const int tid = threadIdx.x;
    const int lane = tid & 31;
    const int w = tid >> 5;
    const int g = lane >> 2;
    const int tig = lane & 3;
    const int qt = gridDim.x - 1 - blockIdx.x;   // heavy tiles first
    const int bh = blockIdx.y;
    const int b = bh >> 4;
    const int hd = bh & 15;
    const int q0 = qt * 128;
    const int qw = q0 + w * 16;

    // K/V cp.async: tile = tid>>7 (0=K from +1024, 1=V from +2048),
    // 2 thr/row, each thread covers rows kv_r and kv_r+64 (128-row stage).
    const int kv_tile = tid >> 7;
    const int kv_r = (tid >> 1) & 63;
    const int kv_h = tid & 1;
    const __half* kv_src_base = qh_g + ((size_t)b * SEQ + kv_r) * 3072
        + (kv_tile ? 2048 : 1024) + hd * 64 + kv_h * 32;
    auto issue_kv = [&](int kt) {
        const uint32_t dst = sb + 16384u + (uint32_t)(kt & 1) * 32768u
                           + (uint32_t)kv_tile * 16384u;
        const __half* src = kv_src_base + (size_t)kt * 128 * 3072;
#pragma unroll
        for (int r2 = 0; r2 < 2; r2++)
#pragma unroll
            for (int c = 0; c < 4; c++)
                cp16(dst + SW128((uint32_t)((kv_r + r2 * 64) * 128 + kv_h * 64 + c * 16)),
                     src + (size_t)r2 * 64 * 3072 + c * 8);
    };

    // Q hi tile: 128 rows x 128B (plain stores; covered by first barrier)
    {
        const int r = tid >> 1;
        const int hf = tid & 1;
        const __half* src = qh_g + ((size_t)b * SEQ + q0 + r) * 3072 + hd * 64 + hf * 32;
#pragma unroll
        for (int c = 0; c < 4; c++)
            *(uint4*)(p + SW128((uint32_t)(r * 128 + hf * 64 + c * 16))) = *(const uint4*)(src + c * 8);
    }

    issue_kv(0); cp_commit();

    float S[32], O[32];
#pragma unroll
    for (int i = 0; i < 32; i++) O[i] = 0.f;
    float m0 = -CUDART_INF_F, m1 = -CUDART_INF_F, l0 = 0.f, l1 = 0.f;

    const int ktmax = qt + 1;
#pragma unroll 1
    for (int kt = 0; kt < ktmax; kt++) {
        cp_wait0();              // K/V stage kt resident
        __syncthreads();         // visible to all; all done with stage kt-1
        if (kt + 1 < ktmax) issue_kv(kt + 1);   // overlaps compute of kt
        cp_commit();

        const uint32_t Kb = sb + 16384u + (uint32_t)(kt & 1) * 32768u;
        const uint32_t Vb = Kb + 16384u;

#pragma unroll 1
        for (int hh = 0; hh < 2; hh++) {
            const int k0 = kt * 128 + hh * 64;
            if (k0 > qw + 15) continue;
            const uint32_t KH = Kb + (uint32_t)hh * 8192u;
            const uint32_t VH = Vb + (uint32_t)hh * 8192u;

#pragma unroll
            for (int i = 0; i < 32; i++) S[i] = 0.f;
            // ---- S = Qh·Kh
#pragma unroll
            for (int kat = 0; kat < 4; kat++) {
                const uint32_t swzA = SW128((uint32_t)((w * 16 + (lane & 15)) * 128
                                       + kat * 32 + ((lane >> 4) << 4)));
                uint32_t aqh[4];
                ldsm_x4(aqh, QH + swzA);
#pragma unroll
                for (int j2 = 0; j2 < 4; j2++) {
                    const uint32_t swzB = SW128((uint32_t)((j2 * 16 + ((lane >> 4) & 1) * 8
                                            + (lane & 7)) * 128 + kat * 32 + ((lane >> 3) & 1) * 16));
                    uint32_t bkh[4];
                    ldsm_x4(bkh, KH + swzB);
                    mma16816(&S[(2 * j2) * 4], aqh, bkh);
                    mma16816(&S[(2 * j2 + 1) * 4], aqh, bkh + 2);
                }
            }
            // ---- scale + causal mask + online softmax
            const int row0 = qw + g, row1 = row0 + 8;
            const bool msk = (k0 + 63 > qw);
            float tm0 = -CUDART_INF_F, tm1 = -CUDART_INF_F;
#pragma unroll
            for (int j = 0; j < 8; j++) {
                float* sj = &S[j * 4];
                sj[0] *= 0.125f; sj[1] *= 0.125f; sj[2] *= 0.125f; sj[3] *= 0.125f;
                if (msk) {
                    const int c0 = k0 + j * 8 + 2 * tig;
                    if (c0 > row0)     sj[0] = -CUDART_INF_F;
                    if (c0 + 1 > row0) sj[1] = -CUDART_INF_F;
                    if (c0 > row1)     sj[2] = -CUDART_INF_F;
                    if (c0 + 1 > row1) sj[3] = -CUDART_INF_F;
                }
                tm0 = fmaxf(tm0, fmaxf(sj[0], sj[1]));
                tm1 = fmaxf(tm1, fmaxf(sj[2], sj[3]));
            }
            tm0 = fmaxf(tm0, __shfl_xor_sync(0xffffffffu, tm0, 1));
            tm0 = fmaxf(tm0, __shfl_xor_sync(0xffffffffu, tm0, 2));
            tm1 = fmaxf(tm1, __shfl_xor_sync(0xffffffffu, tm1, 1));
            tm1 = fmaxf(tm1, __shfl_xor_sync(0xffffffffu, tm1, 2));
            const float mn0 = fmaxf(m0, tm0), mn1 = fmaxf(m1, tm1);
            const float corr0 = __expf(m0 - mn0), corr1 = __expf(m1 - mn1);
            m0 = mn0; m1 = mn1;

            float ls0 = 0.f, ls1 = 0.f;
            uint32_t PHf[16];
#pragma unroll
            for (int j = 0; j < 8; j++) {
                const float e0 = __expf(S[j * 4 + 0] - mn0);
                const float e1 = __expf(S[j * 4 + 1] - mn0);
                const float e2 = __expf(S[j * 4 + 2] - mn1);
                const float e3 = __expf(S[j * 4 + 3] - mn1);
                ls0 += e0 + e1; ls1 += e2 + e3;
                PHf[j * 2 + 0] = pack2h(e0, e1);
                PHf[j * 2 + 1] = pack2h(e2, e3);
            }
            ls0 += __shfl_xor_sync(0xffffffffu, ls0, 1);
            ls0 += __shfl_xor_sync(0xffffffffu, ls0, 2);
            ls1 += __shfl_xor_sync(0xffffffffu, ls1, 1);
            ls1 += __shfl_xor_sync(0xffffffffu, ls1, 2);
            l0 = l0 * corr0 + ls0;
            l1 = l1 * corr1 + ls1;
#pragma unroll
            for (int j = 0; j < 8; j++) {
                O[j * 4 + 0] *= corr0; O[j * 4 + 1] *= corr0;
                O[j * 4 + 2] *= corr1; O[j * 4 + 3] *= corr1;
            }
            // ---- O += Ph·Vh   (V^T via ldmatrix.trans)
#pragma unroll
            for (int kat = 0; kat < 4; kat++) {
#pragma unroll
                for (int jd2 = 0; jd2 < 4; jd2++) {
                    const uint32_t swzV = SW128((uint32_t)((kat * 16 + ((lane >> 3) & 1) * 8
                                            + (lane & 7)) * 128 + jd2 * 32 + ((lane >> 4) & 1) * 16));
                    uint32_t bvh[4];
                    ldsm_x4_t(bvh, VH + swzV);
                    mma16816(&O[(2 * jd2) * 4], &PHf[4 * kat], bvh);
                    mma16816(&O[(2 * jd2 + 1) * 4], &PHf[4 * kat], bvh + 2);
                }
            }
        }
    }

    // epilogue: normalized O -> plain fp16 ctx rows (width 1024)
    const float inv0 = 1.f / l0, inv1 = 1.f / l1;
    __half* rp0 = ctx + ((size_t)b * SEQ + qw + g) * HID + hd * 64;
    __half* rp1 = rp0 + (size_t)8 * HID;
#pragma unroll
    for (int j = 0; j < 8; j++) {
        const int c = j * 8 + 2 * tig;
        *(uint32_t*)(rp0 + c) = pack2h(O[j * 4 + 0] * inv0, O[j * 4 + 1] * inv0);
        *(uint32_t*)(rp1 + c) = pack2h(O[j * 4 + 2] * inv1, O[j * 4 + 3] * inv1);
    }
}

// ---------------------------------------------------------------------------
extern "C" void kernel_launch(void* const* d_in, const int* in_sizes, int n_in,
                              void* d_out, int out_size)
{
    (void)in_sizes; (void)n_in; (void)out_size;
    const float* x     = (const float*)d_in[0];
    const float* W_qkv = (const float*)d_in[2];
    const float* b_qkv = (const float*)d_in[3];
    const float* W_out = (const float*)d_in[4];
    const float* b_out = (const float*)d_in[5];
    float* out = (float*)d_out;

    __half *xh, *wqkv, *ctx, *wout, *qh;
    cudaGetSymbolAddress((void**)&xh, g_xh);
    cudaGetSymbolAddress((void**)&wqkv, g_wqkv);
    cudaGetSymbolAddress((void**)&ctx, g_ctx);
    cudaGetSymbolAddress((void**)&wout, g_wout);
    cudaGetSymbolAddress((void**)&qh, g_qh);

    const int gsmem = 97 * 1024;   // 3x32KB ring + align
    const int asmem = 83 * 1024;   // 16KB Q + 2x32KB KV + align
    cudaFuncSetAttribute(gemm_mma_kernel, cudaFuncAttributeMaxDynamicSharedMemorySize, gsmem);
    cudaFuncSetAttribute(gemm_mma_kernel, cudaFuncAttributePreferredSharedMemoryCarveout, 100);
    cudaFuncSetAttribute(attn_mma_kernel, cudaFuncAttributeMaxDynamicSharedMemorySize, asmem);
    cudaFuncSetAttribute(attn_mma_kernel, cudaFuncAttributePreferredSharedMemoryCarveout, 100);

    // 0) all fp32 -> fp16 conversions in ONE launch
    const size_t n0 = (size_t)BT * HID;
    const size_t n1 = (size_t)3 * HID * HID;
    const size_t n2 = (size_t)HID * HID;
    const size_t tot4 = (n0 + n1 + n2) / 4;
    conv3_kernel<<<(unsigned)((tot4 + 255) / 256), 256>>>(
        x, xh, n0, W_qkv, wqkv, n1, W_out, wout, n2);

    // 1) QKV projection (HMMA fp16, K=1024) -> qkv hi
    gemm_mma_kernel<<<dim3(3 * HID / 128, BT / 128), 256, gsmem>>>(
        xh, wqkv, b_qkv, nullptr, qh, 3 * HID, HID);

    // 2) fused causal attention (HMMA fp16, TK=128) -> fp16 ctx
    attn_mma_kernel<<<dim3(SEQ / 128, 4 * NHEADS), 256, asmem>>>(qh, ctx);

    // 3) output projection (HMMA fp16, K=1024) -> fp32 out
    gemm_mma_kernel<<<dim3(HID / 128, BT / 128), 256, gsmem>>>(
        ctx, wout, b_out, out, nullptr, HID, HID);
}

// round 17
// speedup vs baseline: 1.8398x; 1.0039x over previous
#include <cuda_runtime.h>
#include <cuda_fp16.h>
#include <math_constants.h>
#include <cstdint>

#define HID 1024
#define NHEADS 16
#define HDIM 64
#define SEQ 2048
#define BT 8192

// ---------------------------------------------------------------------------
// Scratch (__device__ globals: runtime allocation is forbidden)
// ---------------------------------------------------------------------------
__device__ __half g_xh[(size_t)BT * HID];          // x hi (fp16)
__device__ __half g_wqkv[(size_t)3 * HID * HID];   // W_qkv hi (fp16)
__device__ __half g_ctx[(size_t)BT * HID];         // ctx (fp16)
__device__ __half g_wout[(size_t)HID * HID];       // W_out hi (fp16)
__device__ __half g_qh[(size_t)BT * 3 * HID];      // qkv hi (fp16)

// ---------------------------------------------------------------------------
// helpers
// ---------------------------------------------------------------------------
__device__ __forceinline__ uint32_t smem_to_u32(const void* p) {
    uint32_t a;
    asm("{ .reg .u64 t; cvta.to.shared.u64 t, %1; cvt.u32.u64 %0, t; }"
        : "=r"(a) : "l"(p));
    return a;
}
#define SW128(b) ((b) ^ (((b) >> 3) & 0x70u))

__device__ __forceinline__ void ldsm_x4(uint32_t* r, uint32_t addr) {
    asm volatile("ldmatrix.sync.aligned.m8n8.x4.shared.b16 {%0,%1,%2,%3}, [%4];"
        : "=r"(r[0]), "=r"(r[1]), "=r"(r[2]), "=r"(r[3]) : "r"(addr));
}
__device__ __forceinline__ void ldsm_x4_t(uint32_t* r, uint32_t addr) {
    asm volatile("ldmatrix.sync.aligned.m8n8.x4.trans.shared.b16 {%0,%1,%2,%3}, [%4];"
        : "=r"(r[0]), "=r"(r[1]), "=r"(r[2]), "=r"(r[3]) : "r"(addr));
}
__device__ __forceinline__ void mma16816(float* d, const uint32_t* a, const uint32_t* b) {
    asm volatile("mma.sync.aligned.m16n8k16.row.col.f32.f16.f16.f32 "
        "{%0,%1,%2,%3}, {%4,%5,%6,%7}, {%8,%9}, {%0,%1,%2,%3};"
        : "+f"(d[0]), "+f"(d[1]), "+f"(d[2]), "+f"(d[3])
        : "r"(a[0]), "r"(a[1]), "r"(a[2]), "r"(a[3]), "r"(b[0]), "r"(b[1]));
}
__device__ __forceinline__ void cp16(uint32_t dst, const void* src) {
    asm volatile("cp.async.cg.shared.global [%0], [%1], 16;" :: "r"(dst), "l"(src));
}
__device__ __forceinline__ void cp_commit() { asm volatile("cp.async.commit_group;" ::: "memory"); }
__device__ __forceinline__ void cp_wait1()  { asm volatile("cp.async.wait_group 1;" ::: "memory"); }
__device__ __forceinline__ void cp_wait0()  { asm volatile("cp.async.wait_group 0;" ::: "memory"); }

__device__ __forceinline__ uint32_t pack2h(float a, float b) {
    __half2 t = __floats2half2_rn(a, b);
    return *reinterpret_cast<uint32_t*>(&t);
}

// ---------------------------------------------------------------------------
// Merged flat convert: three fp32 arrays -> fp16, one launch.
// ---------------------------------------------------------------------------
__global__ __launch_bounds__(256) void conv3_kernel(
    const float* __restrict__ s0, __half* __restrict__ d0, size_t n0,
    const float* __restrict__ s1, __half* __restrict__ d1, size_t n1,
    const float* __restrict__ s2, __half* __restrict__ d2, size_t n2)
{
    size_t i = ((size_t)blockIdx.x * blockDim.x + threadIdx.x) * 4;
    const float* s; __half* d; size_t off;
    if (i < n0)                { s = s0; d = d0; off = i; }
    else if (i < n0 + n1)      { s = s1; d = d1; off = i - n0; }
    else if (i < n0 + n1 + n2) { s = s2; d = d2; off = i - n0 - n1; }
    else return;
    float4 v = *(const float4*)(s + off);
    *(uint2*)(d + off) = make_uint2(pack2h(v.x, v.y), pack2h(v.z, v.w));
}

// ---------------------------------------------------------------------------
// mma.sync fp16 GEMM: C[M,N] = A[M,K] @ W[N,K]^T + bias   (K runtime, %64==0)
// CTA 128x128, BK=64, 256 thr (8 warps 2x4), warp tile 64x32.
// 3-stage cp.async ring, one barrier per k-step.
// Epilogue: fp32 (Cf) or fp16 (Ch).
// ---------------------------------------------------------------------------
__global__ __launch_bounds__(256, 2) void gemm_mma_kernel(
    const __half* __restrict__ A2, const __half* __restrict__ W2,
    const float* __restrict__ bias, float* __restrict__ Cf,
    __half* __restrict__ Ch, int N, int K)
{
    extern __shared__ char dsm[];
    const uint32_t dyn = smem_to_u32(dsm);
    const uint32_t base = (dyn + 1023u) & ~1023u;

    const int tid = threadIdx.x;
    const int lane = tid & 31;
    const int wid = tid >> 5;
    const int wm = wid >> 2;
    const int wn = wid & 3;
    const size_t m0 = (size_t)blockIdx.y * 128;
    const size_t n0 = (size_t)blockIdx.x * 128;
    const int ksteps = K >> 6;

    const int arow = tid >> 1;
    const int ahalf = tid & 1;
    const __half* gA = A2 + (m0 + arow) * (size_t)K + ahalf * 32;
    const __half* gB = W2 + (n0 + arow) * (size_t)K + ahalf * 32;
    const uint32_t sts = (uint32_t)(arow * 128 + ahalf * 64);

    float acc[4][4][4];
#pragma unroll
    for (int i = 0; i < 4; i++)
#pragma unroll
        for (int j = 0; j < 4; j++)
#pragma unroll
            for (int r = 0; r < 4; r++) acc[i][j][r] = 0.f;

    auto issue = [&](int s) {
        const uint32_t ab = base + (uint32_t)(s % 3) * 32768u;
        const int k0 = s * 64;
#pragma unroll
        for (int c = 0; c < 4; c++) {
            const uint32_t sw = SW128(sts + (uint32_t)c * 16u);
            cp16(ab + sw, gA + k0 + c * 8);
            cp16(ab + 16384u + sw, gB + k0 + c * 8);
        }
    };

    issue(0); cp_commit();
    issue(1); cp_commit();

#pragma unroll 1
    for (int s = 0; s < ksteps; s++) {
        cp_wait1();              // stage s resident (stage s+1 may be pending)
        __syncthreads();         // all warps see stage s; all done with stage s-1
        if (s + 2 < ksteps) issue(s + 2);   // ring distance 2
        cp_commit();

        const uint32_t abase = base + (uint32_t)(s % 3) * 32768u;
        const uint32_t bbase = abase + 16384u;
#pragma unroll
        for (int kat = 0; kat < 4; kat++) {
            uint32_t af[4][4], bf[4][2];
#pragma unroll
            for (int i = 0; i < 4; i++) {
                uint32_t row = (uint32_t)(wm * 64 + i * 16 + (lane & 15));
                uint32_t byte = row * 128u + (uint32_t)kat * 32u + ((lane >> 4) << 4);
                ldsm_x4(af[i], abase + SW128(byte));
            }
#pragma unroll
            for (int jj = 0; jj < 2; jj++) {
                uint32_t row = (uint32_t)(wn * 32 + jj * 16 + ((lane >> 4) & 1) * 8 + (lane & 7));
                uint32_t byte = row * 128u + (uint32_t)kat * 32u + (((lane >> 3) & 1) << 4);
                uint32_t t[4];
                ldsm_x4(t, bbase + SW128(byte));
                bf[jj * 2][0] = t[0]; bf[jj * 2][1] = t[1];
                bf[jj * 2 + 1][0] = t[2]; bf[jj * 2 + 1][1] = t[3];
            }
#pragma unroll
            for (int i = 0; i < 4; i++)
#pragma unroll
                for (int j = 0; j < 4; j++)
                    mma16816(acc[i][j], af[i], bf[j]);
        }
    }

    // epilogue
    const int g = lane >> 2;
    const int tig = lane & 3;
#pragma unroll
    for (int i = 0; i < 4; i++) {
        const size_t r0 = m0 + wm * 64 + i * 16 + g;
#pragma unroll
        for (int j = 0; j < 4; j++) {
            const int col = (int)n0 + wn * 32 + j * 8 + tig * 2;
            const float2 bb = *(const float2*)(bias + col);
            const float v0 = acc[i][j][0] + bb.x, v1 = acc[i][j][1] + bb.y;
            const float v2 = acc[i][j][2] + bb.x, v3 = acc[i][j][3] + bb.y;
            if (Cf) {
                *(float2*)(Cf + r0 * N + col) = make_float2(v0, v1);
                *(float2*)(Cf + (r0 + 8) * N + col) = make_float2(v2, v3);
            } else {
                *(uint32_t*)(Ch + r0 * N + col) = pack2h(v0, v1);
                *(uint32_t*)(Ch + (r0 + 8) * N + col) = pack2h(v2, v3);
            }
        }
    }
}

// ---------------------------------------------------------------------------
// Fused causal flash attention on tensor cores (fp16 operands, fp32 softmax).
// S = 0.125*(Qh·Kh);  O += Ph·Vh.     (round-15 proven configuration)
// grid (16 qtiles, 64 bh), 256 thr (8 warps), warp = 16 q-rows.
// K/V (TK=64) double-buffered cp.async; one barrier per kt-iteration.
// Epilogue emits plain fp16 ctx [BT, HID].
// smem: Qh 16KB + 2 x (Kh,Vh 16KB) = 48KB.
// ---------------------------------------------------------------------------
__global__ __launch_bounds__(256, 2) void attn_mma_kernel(
    const __half* __restrict__ qh_g, __half* __restrict__ ctx)
{
    extern __shared__ char smA[];
    const uint32_t dyn = smem_to_u32(smA);
    const uint32_t sb = (dyn + 1023u) & ~1023u;
    char* p = smA + (sb - dyn);
    const uint32_t QH = sb;

    const int tid = threadIdx.x;
    const int lane = tid & 31;
    const int w = tid >> 5;
    const int g = lane >> 2;
    const int tig = lane & 3;
    const int qt = blockIdx.x;
    const int bh = blockIdx.y;
    const int b = bh >> 4;
    const int hd = bh & 15;
    const int q0 = qt * 128;
    const int qw = q0 + w * 16;

    // K/V cp.async: tile = tid>>7 (0=Kh from +1024, 1=Vh from +2048), 2 thr/row
    const int kv_tile = tid >> 7;
    const int kv_r = (tid >> 1) & 63;
    const int kv_h = tid & 1;
    const __half* kv_src_base = qh_g + ((size_t)b * SEQ + kv_r) * 3072
        + (kv_tile ? 2048 : 1024) + hd * 64 + kv_h * 32;
    auto issue_kv = [&](int kt) {
        const uint32_t dst = sb + 16384u + (uint32_t)(kt & 1) * 16384u + (uint32_t)kv_tile * 8192u;
        const __half* src = kv_src_base + (size_t)kt * 64 * 3072;
#pragma unroll
        for (int c = 0; c < 4; c++)
            cp16(dst + SW128((uint32_t)(kv_r * 128 + kv_h * 64 + c * 16)), src + c * 8);
    };

    // Q hi tile: 128 rows x 128B (plain stores; covered by first barrier)
    {
        const int r = tid >> 1;
        const int hf = tid & 1;
        const __half* src = qh_g + ((size_t)b * SEQ + q0 + r) * 3072 + hd * 64 + hf * 32;
#pragma unroll
        for (int c = 0; c < 4; c++)
            *(uint4*)(p + SW128((uint32_t)(r * 128 + hf * 64 + c * 16))) = *(const uint4*)(src + c * 8);
    }

    issue_kv(0); cp_commit();

    float S[32], O[32];
#pragma unroll
    for (int i = 0; i < 32; i++) O[i] = 0.f;
    float m0 = -CUDART_INF_F, m1 = -CUDART_INF_F, l0 = 0.f, l1 = 0.f;

    const int ktmax = 2 * (qt + 1);
#pragma unroll 1
    for (int kt = 0; kt < ktmax; kt++) {
        const int k0 = kt * 64;
        cp_wait0();              // K/V stage kt resident
        __syncthreads();         // visible to all; all done with stage kt-1
        if (kt + 1 < ktmax) issue_kv(kt + 1);   // overlaps compute of kt
        cp_commit();

        const uint32_t kvb = sb + 16384u + (uint32_t)(kt & 1) * 16384u;
        const uint32_t KH = kvb, VH = kvb + 8192u;

        if (k0 <= qw + 15) {
#pragma unroll
            for (int i = 0; i < 32; i++) S[i] = 0.f;
            // ---- S = Qh·Kh
#pragma unroll
            for (int kat = 0; kat < 4; kat++) {
                const uint32_t swzA = SW128((uint32_t)((w * 16 + (lane & 15)) * 128
                                       + kat * 32 + ((lane >> 4) << 4)));
                uint32_t aqh[4];
                ldsm_x4(aqh, QH + swzA);
#pragma unroll
                for (int j2 = 0; j2 < 4; j2++) {
                    const uint32_t swzB = SW128((uint32_t)((j2 * 16 + ((lane >> 4) & 1) * 8
                                            + (lane & 7)) * 128 + kat * 32 + ((lane >> 3) & 1) * 16));
                    uint32_t bkh[4];
                    ldsm_x4(bkh, KH + swzB);
                    mma16816(&S[(2 * j2) * 4], aqh, bkh);
                    mma16816(&S[(2 * j2 + 1) * 4], aqh, bkh + 2);
                }
            }
            // ---- scale + causal mask + online softmax
            const int row0 = qw + g, row1 = row0 + 8;
            const bool msk = (k0 + 63 > qw);
            float tm0 = -CUDART_INF_F, tm1 = -CUDART_INF_F;
#pragma unroll
            for (int j = 0; j < 8; j++) {
                float* sj = &S[j * 4];
                sj[0] *= 0.125f; sj[1] *= 0.125f; sj[2] *= 0.125f; sj[3] *= 0.125f;
                if (msk) {
                    const int c0 = k0 + j * 8 + 2 * tig;
                    if (c0 > row0)     sj[0] = -CUDART_INF_F;
                    if (c0 + 1 > row0) sj[1] = -CUDART_INF_F;
                    if (c0 > row1)     sj[2] = -CUDART_INF_F;
                    if (c0 + 1 > row1) sj[3] = -CUDART_INF_F;
                }
                tm0 = fmaxf(tm0, fmaxf(sj[0], sj[1]));
                tm1 = fmaxf(tm1, fmaxf(sj[2], sj[3]));
            }
            tm0 = fmaxf(tm0, __shfl_xor_sync(0xffffffffu, tm0, 1));
            tm0 = fmaxf(tm0, __shfl_xor_sync(0xffffffffu, tm0, 2));
            tm1 = fmaxf(tm1, __shfl_xor_sync(0xffffffffu, tm1, 1));
            tm1 = fmaxf(tm1, __shfl_xor_sync(0xffffffffu, tm1, 2));
            const float mn0 = fmaxf(m0, tm0), mn1 = fmaxf(m1, tm1);
            const float corr0 = __expf(m0 - mn0), corr1 = __expf(m1 - mn1);
            m0 = mn0; m1 = mn1;

            float ls0 = 0.f, ls1 = 0.f;
            uint32_t PHf[16];
#pragma unroll
            for (int j = 0; j < 8; j++) {
                const float e0 = __expf(S[j * 4 + 0] - mn0);
                const float e1 = __expf(S[j * 4 + 1] - mn0);
                const float e2 = __expf(S[j * 4 + 2] - mn1);
                const float e3 = __expf(S[j * 4 + 3] - mn1);
                ls0 += e0 + e1; ls1 += e2 + e3;
                PHf[j * 2 + 0] = pack2h(e0, e1);
                PHf[j * 2 + 1] = pack2h(e2, e3);
            }
            ls0 += __shfl_xor_sync(0xffffffffu, ls0, 1);
            ls0 += __shfl_xor_sync(0xffffffffu, ls0, 2);
            ls1 += __shfl_xor_sync(0xffffffffu, ls1, 1);
            ls1 += __shfl_xor_sync(0xffffffffu, ls1, 2);
            l0 = l0 * corr0 + ls0;
            l1 = l1 * corr1 + ls1;
#pragma unroll
            for (int j = 0; j < 8; j++) {
                O[j * 4 + 0] *= corr0; O[j * 4 + 1] *= corr0;
                O[j * 4 + 2] *= corr1; O[j * 4 + 3] *= corr1;
            }
            // ---- O += Ph·Vh   (V^T via ldmatrix.trans)
#pragma unroll
            for (int kat = 0; kat < 4; kat++) {
#pragma unroll
                for (int jd2 = 0; jd2 < 4; jd2++) {
                    const uint32_t swzV = SW128((uint32_t)((kat * 16 + ((lane >> 3) & 1) * 8
                                            + (lane & 7)) * 128 + jd2 * 32 + ((lane >> 4) & 1) * 16));
                    uint32_t bvh[4];
                    ldsm_x4_t(bvh, VH + swzV);
                    mma16816(&O[(2 * jd2) * 4], &PHf[4 * kat], bvh);
                    mma16816(&O[(2 * jd2 + 1) * 4], &PHf[4 * kat], bvh + 2);
                }
            }
        }
    }

    // epilogue: normalized O -> plain fp16 ctx rows (width 1024)
    const float inv0 = 1.f / l0, inv1 = 1.f / l1;
    __half* rp0 = ctx + ((size_t)b * SEQ + qw + g) * HID + hd * 64;
    __half* rp1 = rp0 + (size_t)8 * HID;
#pragma unroll
    for (int j = 0; j < 8; j++) {
        const int c = j * 8 + 2 * tig;
        *(uint32_t*)(rp0 + c) = pack2h(O[j * 4 + 0] * inv0, O[j * 4 + 1] * inv0);
        *(uint32_t*)(rp1 + c) = pack2h(O[j * 4 + 2] * inv1, O[j * 4 + 3] * inv1);
    }
}

// ---------------------------------------------------------------------------
extern "C" void kernel_launch(void* const* d_in, const int* in_sizes, int n_in,
                              void* d_out, int out_size)
{
    (void)in_sizes; (void)n_in; (void)out_size;
    const float* x     = (const float*)d_in[0];
    const float* W_qkv = (const float*)d_in[2];
    const float* b_qkv = (const float*)d_in[3];
    const float* W_out = (const float*)d_in[4];
    const float* b_out = (const float*)d_in[5];
    float* out = (float*)d_out;

    __half *xh, *wqkv, *ctx, *wout, *qh;
    cudaGetSymbolAddress((void**)&xh, g_xh);
    cudaGetSymbolAddress((void**)&wqkv, g_wqkv);
    cudaGetSymbolAddress((void**)&ctx, g_ctx);
    cudaGetSymbolAddress((void**)&wout, g_wout);
    cudaGetSymbolAddress((void**)&qh, g_qh);

    const int gsmem = 97 * 1024;   // 3x32KB ring + align
    const int asmem = 50 * 1024;   // 16KB Q + 2x16KB KV + align
    cudaFuncSetAttribute(gemm_mma_kernel, cudaFuncAttributeMaxDynamicSharedMemorySize, gsmem);
    cudaFuncSetAttribute(gemm_mma_kernel, cudaFuncAttributePreferredSharedMemoryCarveout, 100);
    cudaFuncSetAttribute(attn_mma_kernel, cudaFuncAttributeMaxDynamicSharedMemorySize, asmem);
    cudaFuncSetAttribute(attn_mma_kernel, cudaFuncAttributePreferredSharedMemoryCarveout, 100);

    // 0) all fp32 -> fp16 conversions in ONE launch
    const size_t n0 = (size_t)BT * HID;
    const size_t n1 = (size_t)3 * HID * HID;
    const size_t n2 = (size_t)HID * HID;
    const size_t tot4 = (n0 + n1 + n2) / 4;
    conv3_kernel<<<(unsigned)((tot4 + 255) / 256), 256>>>(
        x, xh, n0, W_qkv, wqkv, n1, W_out, wout, n2);

    // 1) QKV projection (HMMA fp16, K=1024) -> qkv hi
    gemm_mma_kernel<<<dim3(3 * HID / 128, BT / 128), 256, gsmem>>>(
        xh, wqkv, b_qkv, nullptr, qh, 3 * HID, HID);

    // 2) fused causal attention (HMMA fp16, TK=64) -> fp16 ctx
    attn_mma_kernel<<<dim3(SEQ / 128, 4 * NHEADS), 256, asmem>>>(qh, ctx);

    // 3) output projection (HMMA fp16, K=1024) -> fp32 out
    gemm_mma_kernel<<<dim3(HID / 128, BT / 128), 256, gsmem>>>(
        ctx, wout, b_out, out, nullptr, HID, HID);
}